// round 1
// baseline (speedup 1.0000x reference)
#include <cuda_runtime.h>
#include <math.h>

namespace {

constexpr int B_ = 8, C_ = 512, L_ = 256;
constexpr int CL_ = C_ * L_;           // 131072
constexpr int C4_ = 4 * C_;            // 2048
constexpr int NR_ = L_ * B_;           // 2048
constexpr float SCALE_ = 0.044194173824159216f; // 512^-0.5

// ---------------- scratch (static device memory, no allocs) ----------------
constexpr size_t OFF_THETA = 0;
constexpr size_t OFF_PHI   = OFF_THETA + (size_t)B_ * CL_;
constexpr size_t OFF_G     = OFF_PHI   + (size_t)B_ * CL_;
constexpr size_t OFF_SG    = OFF_G     + (size_t)B_ * CL_;
constexpr size_t OFF_SL    = OFF_SG    + (size_t)B_ * L_ * L_;
constexpr size_t OFF_GBAR  = OFF_SL    + (size_t)B_ * L_ * L_;
constexpr size_t OFF_GATE  = OFF_GBAR  + (size_t)B_ * L_;
constexpr size_t OFF_GOUT  = OFF_GATE  + (size_t)B_ * L_;
constexpr size_t OFF_GOUT2 = OFF_GOUT  + (size_t)B_ * CL_;
constexpr size_t OFF_H1    = OFF_GOUT2 + (size_t)B_ * CL_;
constexpr size_t OFF_M1    = OFF_H1    + (size_t)NR_ * C_;
constexpr size_t OFF_M2    = OFF_M1    + (size_t)NR_ * C4_;
constexpr size_t SCRATCH_TOTAL = OFF_M2 + (size_t)NR_ * C_;

} // namespace

__device__ float d_scratch[SCRATCH_TOTAL];

namespace {

// ---------------- reduction helpers ----------------
__device__ __forceinline__ float warpSum(float v) {
#pragma unroll
    for (int o = 16; o; o >>= 1) v += __shfl_xor_sync(0xffffffffu, v, o);
    return v;
}
__device__ __forceinline__ float warpMax(float v) {
#pragma unroll
    for (int o = 16; o; o >>= 1) v = fmaxf(v, __shfl_xor_sync(0xffffffffu, v, o));
    return v;
}

__device__ __forceinline__ float apply_act(float v, int act) {
    if (act == 1) { // Mish: v * tanh(softplus(v)), numerically stable softplus
        float sp = fmaxf(v, 0.f) + log1pf(__expf(-fabsf(v)));
        v = v * tanhf(sp);
    }
    return v;
}

// ============================================================================
// GEMM kernels.
// Operand modes:
//   AMODE 0: A is [M,K] with K contiguous (row stride = lda)   -> Y += A[m,k]*...
//   AMODE 1: A is [K,M] with M contiguous (row stride = lda)   -> "transposed A"
//   BMODE 0: B is [N,K] with K contiguous                      -> Y = A * B^T
//   BMODE 1: B is [K,N] with N contiguous                      -> Y = A * B
// Y[m,n] = act( scale * sum_k a(m,k)*b(k,n) + biasM[m] + biasN[n] )
// All dims assumed divisible by the tile sizes (true for this problem).
// ============================================================================

// ---- 128x128x8 tile, 256 threads, 8x8 per thread (for big GEMMs) ----
template <int AMODE, int BMODE>
__global__ void __launch_bounds__(256, 2) gemm128(
    const float* __restrict__ A, const float* __restrict__ Bm, float* __restrict__ Y,
    int M, int N, int K, int lda, int ldb, int ldy,
    size_t sA, size_t sB, size_t sY,
    const float* __restrict__ biasM, const float* __restrict__ biasN,
    float scale, int act)
{
    __shared__ float As[8][128];
    __shared__ float Bs[8][128];
    A  += (size_t)blockIdx.z * sA;
    Bm += (size_t)blockIdx.z * sB;
    Y  += (size_t)blockIdx.z * sY;
    const int m0 = blockIdx.y * 128, n0 = blockIdx.x * 128;
    const int tid = threadIdx.x;
    const int ty = tid >> 4, tx = tid & 15;
    const int ra = ty * 4, cb = tx * 4;

    float acc[8][8];
#pragma unroll
    for (int i = 0; i < 8; i++)
#pragma unroll
        for (int j = 0; j < 8; j++) acc[i][j] = 0.f;

    for (int k0 = 0; k0 < K; k0 += 8) {
        if (AMODE == 0) {
            int ml = tid >> 1, kl = (tid & 1) * 4;
            float4 v = *(const float4*)(A + (size_t)(m0 + ml) * lda + k0 + kl);
            As[kl + 0][ml] = v.x; As[kl + 1][ml] = v.y;
            As[kl + 2][ml] = v.z; As[kl + 3][ml] = v.w;
        } else {
            int k = tid >> 5, ml = (tid & 31) * 4;
            *(float4*)(&As[k][ml]) = *(const float4*)(A + (size_t)(k0 + k) * lda + m0 + ml);
        }
        if (BMODE == 0) {
            int nl = tid >> 1, kl = (tid & 1) * 4;
            float4 v = *(const float4*)(Bm + (size_t)(n0 + nl) * ldb + k0 + kl);
            Bs[kl + 0][nl] = v.x; Bs[kl + 1][nl] = v.y;
            Bs[kl + 2][nl] = v.z; Bs[kl + 3][nl] = v.w;
        } else {
            int k = tid >> 5, nl = (tid & 31) * 4;
            *(float4*)(&Bs[k][nl]) = *(const float4*)(Bm + (size_t)(k0 + k) * ldb + n0 + nl);
        }
        __syncthreads();
#pragma unroll
        for (int k = 0; k < 8; k++) {
            float a[8], bb[8];
            *(float4*)(a)      = *(const float4*)&As[k][ra];
            *(float4*)(a + 4)  = *(const float4*)&As[k][ra + 64];
            *(float4*)(bb)     = *(const float4*)&Bs[k][cb];
            *(float4*)(bb + 4) = *(const float4*)&Bs[k][cb + 64];
#pragma unroll
            for (int i = 0; i < 8; i++)
#pragma unroll
                for (int j = 0; j < 8; j++)
                    acc[i][j] = fmaf(a[i], bb[j], acc[i][j]);
        }
        __syncthreads();
    }

#pragma unroll
    for (int i = 0; i < 8; i++) {
        int m = m0 + ((i < 4) ? (ra + i) : (64 + ra + i - 4));
        float bmv = biasM ? biasM[m] : 0.f;
#pragma unroll
        for (int jg = 0; jg < 2; jg++) {
            int n = n0 + cb + jg * 64;
            float4 o;
            float* po = &o.x;
#pragma unroll
            for (int j = 0; j < 4; j++) {
                float v = acc[i][jg * 4 + j] * scale + bmv;
                if (biasN) v += biasN[n + j];
                po[j] = apply_act(v, act);
            }
            *(float4*)(Y + (size_t)m * ldy + n) = o;
        }
    }
}

// ---- 64x64x16 tile, 256 threads, 4x4 per thread (for smaller GEMMs) ----
template <int AMODE, int BMODE>
__global__ void __launch_bounds__(256) gemm64(
    const float* __restrict__ A, const float* __restrict__ Bm, float* __restrict__ Y,
    int M, int N, int K, int lda, int ldb, int ldy,
    size_t sA, size_t sB, size_t sY,
    const float* __restrict__ biasM, const float* __restrict__ biasN,
    float scale, int act)
{
    __shared__ float As[16][64];
    __shared__ float Bs[16][64];
    A  += (size_t)blockIdx.z * sA;
    Bm += (size_t)blockIdx.z * sB;
    Y  += (size_t)blockIdx.z * sY;
    const int m0 = blockIdx.y * 64, n0 = blockIdx.x * 64;
    const int tid = threadIdx.x;
    const int ty = tid >> 4, tx = tid & 15;
    const int ra = ty * 4, cb = tx * 4;

    float acc[4][4];
#pragma unroll
    for (int i = 0; i < 4; i++)
#pragma unroll
        for (int j = 0; j < 4; j++) acc[i][j] = 0.f;

    for (int k0 = 0; k0 < K; k0 += 16) {
        if (AMODE == 0) {
            int ml = tid >> 2, kl = (tid & 3) * 4;
            float4 v = *(const float4*)(A + (size_t)(m0 + ml) * lda + k0 + kl);
            As[kl + 0][ml] = v.x; As[kl + 1][ml] = v.y;
            As[kl + 2][ml] = v.z; As[kl + 3][ml] = v.w;
        } else {
            int k = tid >> 4, ml = (tid & 15) * 4;
            *(float4*)(&As[k][ml]) = *(const float4*)(A + (size_t)(k0 + k) * lda + m0 + ml);
        }
        if (BMODE == 0) {
            int nl = tid >> 2, kl = (tid & 3) * 4;
            float4 v = *(const float4*)(Bm + (size_t)(n0 + nl) * ldb + k0 + kl);
            Bs[kl + 0][nl] = v.x; Bs[kl + 1][nl] = v.y;
            Bs[kl + 2][nl] = v.z; Bs[kl + 3][nl] = v.w;
        } else {
            int k = tid >> 4, nl = (tid & 15) * 4;
            *(float4*)(&Bs[k][nl]) = *(const float4*)(Bm + (size_t)(k0 + k) * ldb + n0 + nl);
        }
        __syncthreads();
#pragma unroll
        for (int k = 0; k < 16; k++) {
            float4 a = *(const float4*)&As[k][ra];
            float4 b = *(const float4*)&Bs[k][cb];
            const float av[4] = {a.x, a.y, a.z, a.w};
            const float bv[4] = {b.x, b.y, b.z, b.w};
#pragma unroll
            for (int i = 0; i < 4; i++)
#pragma unroll
                for (int j = 0; j < 4; j++)
                    acc[i][j] = fmaf(av[i], bv[j], acc[i][j]);
        }
        __syncthreads();
    }

#pragma unroll
    for (int i = 0; i < 4; i++) {
        int m = m0 + ra + i;
        float bmv = biasM ? biasM[m] : 0.f;
        int n = n0 + cb;
        float4 o;
        float* po = &o.x;
#pragma unroll
        for (int j = 0; j < 4; j++) {
            float v = acc[i][j] * scale + bmv;
            if (biasN) v += biasN[n + j];
            po[j] = apply_act(v, act);
        }
        *(float4*)(Y + (size_t)m * ldy + n) = o;
    }
}

// ============================================================================
// gbar[b,m] = mean_c g[b,c,m]   (one block per batch, thread m, coalesced)
// ============================================================================
__global__ void gbar_kernel(const float* __restrict__ g, float* __restrict__ gbar)
{
    int b = blockIdx.x, m = threadIdx.x;
    const float* p = g + (size_t)b * CL_ + m;
    float s = 0.f;
#pragma unroll 8
    for (int c = 0; c < C_; c++) s += p[(size_t)c * L_];
    gbar[b * L_ + m] = s * (1.f / C_);
}

// ============================================================================
// Row softmax over last dim (L_=256), in place. One block (256 thr) per row.
// ============================================================================
__global__ void softmax256(float* __restrict__ S)
{
    __shared__ float sm[16];
    int row = blockIdx.x, tid = threadIdx.x;
    int lane = tid & 31, w = tid >> 5;
    float v = S[(size_t)row * L_ + tid];
    float m = warpMax(v);
    if (lane == 0) sm[w] = m;
    __syncthreads();
    float M = -1e30f;
#pragma unroll
    for (int i = 0; i < 8; i++) M = fmaxf(M, sm[i]);
    float e = __expf(v - M);
    float s = warpSum(e);
    if (lane == 0) sm[8 + w] = s;
    __syncthreads();
    float T = 0.f;
#pragma unroll
    for (int i = 0; i < 8; i++) T += sm[8 + i];
    S[(size_t)row * L_ + tid] = e / T;
}

// ============================================================================
// Local attention gate. One warp per (b,l).
// scores[w] = Sl[b,l, l+w-32] if valid else 0 (zeros DO participate in softmax)
// pooled    = sum_w p[w] * gbar[b, l+w-32] (0 if invalid)
// gate      = sigmoid(wl_w * pooled + wl_b)
// ============================================================================
__global__ void local_gate_kernel(const float* __restrict__ Sl,
                                  const float* __restrict__ gbar,
                                  const float* __restrict__ wlw,
                                  const float* __restrict__ wlb,
                                  float* __restrict__ gate)
{
    int b = blockIdx.y;
    int l = blockIdx.x * 4 + (threadIdx.x >> 5);
    int lane = threadIdx.x & 31;
    const float* srow = Sl + ((size_t)b * L_ + l) * L_;
    const float* gb = gbar + (size_t)b * L_;

    int m0 = l + lane - 32;      // w = lane
    int m1 = l + lane;           // w = lane + 32
    bool v0 = (m0 >= 0) && (m0 < L_);
    bool v1 = (m1 >= 0) && (m1 < L_);
    float s0 = v0 ? srow[m0] : 0.f;
    float s1 = v1 ? srow[m1] : 0.f;
    float g0 = v0 ? gb[m0] : 0.f;
    float g1 = v1 ? gb[m1] : 0.f;

    float mx = warpMax(fmaxf(s0, s1));
    float e0 = __expf(s0 - mx), e1 = __expf(s1 - mx);
    float num = warpSum(e0 * g0 + e1 * g1);
    float den = warpSum(e0 + e1);
    if (lane == 0) {
        float pooled = num / den;
        float z = wlw[0] * pooled + wlb[0];
        gate[b * L_ + l] = 1.f / (1.f + __expf(-z));
    }
}

// ============================================================================
// LN1: h = gout2*gate + x (over C for fixed (l,b)), write h1[(l*B+b)*C + c]
// One block (256 thr) per (l,b); each thread handles c=tid and c=tid+256.
// ============================================================================
__global__ void ln1_kernel(const float* __restrict__ gout2,
                           const float* __restrict__ gate,
                           const float* __restrict__ x,
                           const float* __restrict__ g1, const float* __restrict__ b1,
                           float* __restrict__ h1)
{
    __shared__ float sm[16];
    int l = blockIdx.x, b = blockIdx.y, tid = threadIdx.x;
    int lane = tid & 31, w = tid >> 5;
    float gt = gate[b * L_ + l];
    size_t base = (size_t)b * CL_ + l;
    float v0 = fmaf(gout2[base + (size_t)tid * L_], gt, x[base + (size_t)tid * L_]);
    float v1 = fmaf(gout2[base + (size_t)(tid + 256) * L_], gt, x[base + (size_t)(tid + 256) * L_]);
    float s = warpSum(v0 + v1);
    float q = warpSum(v0 * v0 + v1 * v1);
    if (lane == 0) { sm[w] = s; sm[8 + w] = q; }
    __syncthreads();
    float S = 0.f, Q = 0.f;
#pragma unroll
    for (int i = 0; i < 8; i++) { S += sm[i]; Q += sm[8 + i]; }
    float mean = S * (1.f / C_);
    float var = Q * (1.f / C_) - mean * mean;
    float r = rsqrtf(var + 1e-5f);
    size_t o = ((size_t)l * B_ + b) * C_;
    h1[o + tid]       = (v0 - mean) * r * g1[tid] + b1[tid];
    h1[o + tid + 256] = (v1 - mean) * r * g1[tid + 256] + b1[tid + 256];
}

// ============================================================================
// LN2 + output transpose: out[b,c,l] = LN(m2[row]+h1[row])*g2+b2, row = l*B+b
// ============================================================================
__global__ void ln2_kernel(const float* __restrict__ m2,
                           const float* __restrict__ h1,
                           const float* __restrict__ g2, const float* __restrict__ b2,
                           float* __restrict__ out)
{
    __shared__ float sm[16];
    int row = blockIdx.x, tid = threadIdx.x;
    int lane = tid & 31, w = tid >> 5;
    int l = row / B_, b = row % B_;
    size_t base = (size_t)row * C_;
    float v0 = m2[base + tid] + h1[base + tid];
    float v1 = m2[base + tid + 256] + h1[base + tid + 256];
    float s = warpSum(v0 + v1);
    float q = warpSum(v0 * v0 + v1 * v1);
    if (lane == 0) { sm[w] = s; sm[8 + w] = q; }
    __syncthreads();
    float S = 0.f, Q = 0.f;
#pragma unroll
    for (int i = 0; i < 8; i++) { S += sm[i]; Q += sm[8 + i]; }
    float mean = S * (1.f / C_);
    float var = Q * (1.f / C_) - mean * mean;
    float r = rsqrtf(var + 1e-5f);
    size_t ob = (size_t)b * CL_ + l;
    out[ob + (size_t)tid * L_]         = (v0 - mean) * r * g2[tid] + b2[tid];
    out[ob + (size_t)(tid + 256) * L_] = (v1 - mean) * r * g2[tid + 256] + b2[tid + 256];
}

} // namespace

// ============================================================================
// Host launcher
// ============================================================================
extern "C" void kernel_launch(void* const* d_in, const int* in_sizes, int n_in,
                              void* d_out, int out_size)
{
    (void)in_sizes; (void)n_in; (void)out_size;
    float* scratch = nullptr;
    cudaGetSymbolAddress((void**)&scratch, d_scratch);

    const float* x       = (const float*)d_in[0];
    const float* theta_w = (const float*)d_in[1];
    const float* theta_b = (const float*)d_in[2];
    const float* phi_w   = (const float*)d_in[3];
    const float* phi_b   = (const float*)d_in[4];
    const float* g_w     = (const float*)d_in[5];
    const float* g_b     = (const float*)d_in[6];
    const float* wl_w    = (const float*)d_in[7];
    const float* wl_b    = (const float*)d_in[8];
    const float* wg_w    = (const float*)d_in[9];
    const float* wg_b    = (const float*)d_in[10];
    const float* conv1_w = (const float*)d_in[11];
    const float* conv1_b = (const float*)d_in[12];
    const float* conv2_w = (const float*)d_in[13];
    const float* conv2_b = (const float*)d_in[14];
    const float* ln1_g   = (const float*)d_in[15];
    const float* ln1_b   = (const float*)d_in[16];
    const float* ln2_g   = (const float*)d_in[17];
    const float* ln2_b   = (const float*)d_in[18];
    float* out = (float*)d_out;

    float* th    = scratch + OFF_THETA;
    float* ph    = scratch + OFF_PHI;
    float* gg    = scratch + OFF_G;
    float* Sg    = scratch + OFF_SG;
    float* Sl    = scratch + OFF_SL;
    float* gbar  = scratch + OFF_GBAR;
    float* gate  = scratch + OFF_GATE;
    float* gout  = scratch + OFF_GOUT;
    float* gout2 = scratch + OFF_GOUT2;
    float* h1    = scratch + OFF_H1;
    float* m1    = scratch + OFF_M1;
    float* m2    = scratch + OFF_M2;

    // 1-3) theta/phi/g = W @ x + b   (W:[C,C] k-contig, x:[C,L] n-contig)
    {
        dim3 grid(L_ / 64, C_ / 64, B_);
        gemm64<0, 1><<<grid, 256>>>(theta_w, x, th, C_, L_, C_, C_, L_, L_,
                                    0, CL_, CL_, theta_b, nullptr, 1.f, 0);
        gemm64<0, 1><<<grid, 256>>>(phi_w, x, ph, C_, L_, C_, C_, L_, L_,
                                    0, CL_, CL_, phi_b, nullptr, 1.f, 0);
        gemm64<0, 1><<<grid, 256>>>(g_w, x, gg, C_, L_, C_, C_, L_, L_,
                                    0, CL_, CL_, g_b, nullptr, 1.f, 0);
    }

    // 4) Sg = scale * phi^T @ theta   [B, L, L]
    // 5) Sl = scale * phi^T @ g       [B, L, L]
    {
        dim3 grid(L_ / 64, L_ / 64, B_);
        gemm64<1, 1><<<grid, 256>>>(ph, th, Sg, L_, L_, C_, L_, L_, L_,
                                    CL_, CL_, (size_t)L_ * L_, nullptr, nullptr, SCALE_, 0);
        gemm64<1, 1><<<grid, 256>>>(ph, gg, Sl, L_, L_, C_, L_, L_, L_,
                                    CL_, CL_, (size_t)L_ * L_, nullptr, nullptr, SCALE_, 0);
    }

    // 6) gbar = mean_c g
    gbar_kernel<<<B_, L_>>>(gg, gbar);

    // 7) gp = softmax(Sg) over m, in place
    softmax256<<<B_ * L_, 256>>>(Sg);

    // 8) local gate from banded Sl + gbar
    {
        dim3 grid(L_ / 4, B_);
        local_gate_kernel<<<grid, 128>>>(Sl, gbar, wl_w, wl_b, gate);
    }

    // 9) gout[c,l] = sum_m g[c,m] * gp[l,m]   (NT)
    {
        dim3 grid(L_ / 64, C_ / 64, B_);
        gemm64<0, 0><<<grid, 256>>>(gg, Sg, gout, C_, L_, L_, L_, L_, L_,
                                    CL_, (size_t)L_ * L_, CL_, nullptr, nullptr, 1.f, 0);
    }

    // 10) gout2 = wg_w @ gout + wg_b
    {
        dim3 grid(L_ / 64, C_ / 64, B_);
        gemm64<0, 1><<<grid, 256>>>(wg_w, gout, gout2, C_, L_, C_, C_, L_, L_,
                                    0, CL_, CL_, wg_b, nullptr, 1.f, 0);
    }

    // 11) h1 = LN1(gout2*gate + x), layout [L*B, C]
    {
        dim3 grid(L_, B_);
        ln1_kernel<<<grid, 256>>>(gout2, gate, x, ln1_g, ln1_b, h1);
    }

    // 12) m1 = Mish(h1 @ conv1_w^T + conv1_b)   [2048, 2048], K=512 (NT)
    {
        dim3 grid(C4_ / 128, NR_ / 128, 1);
        gemm128<0, 0><<<grid, 256>>>(h1, conv1_w, m1, NR_, C4_, C_, C_, C_, C4_,
                                     0, 0, 0, nullptr, conv1_b, 1.f, 1);
    }

    // 13) m2 = m1 @ conv2_w^T + conv2_b   [2048, 512], K=2048 (NT)
    {
        dim3 grid(C_ / 64, NR_ / 64, 1);
        gemm64<0, 0><<<grid, 256>>>(m1, conv2_w, m2, NR_, C_, C4_, C4_, C4_, C_,
                                    0, 0, 0, nullptr, conv2_b, 1.f, 0);
    }

    // 14) out = LN2(m2 + h1), transposed back to [B,C,L]
    ln2_kernel<<<NR_, 256>>>(m2, h1, ln2_g, ln2_b, out);
}

// round 4
// speedup vs baseline: 1.3275x; 1.3275x over previous
#include <cuda_runtime.h>
#include <cuda_bf16.h>
#include <math.h>
#include <stdint.h>

// ============================================================================
// Problem constants
// ============================================================================
namespace {
constexpr int B_ = 8, C_ = 512, L_ = 256;
constexpr int CL_ = C_ * L_;           // 131072
constexpr int C4_ = 4 * C_;            // 2048
constexpr int NR_ = L_ * B_;           // 2048
constexpr float SCALE_ = 0.044194173824159216f; // 512^-0.5

// ---------------- scratch offsets (floats) ----------------
constexpr size_t OFF_THETA = 0;
constexpr size_t OFF_PHI   = OFF_THETA + (size_t)B_ * CL_;
constexpr size_t OFF_G     = OFF_PHI   + (size_t)B_ * CL_;
constexpr size_t OFF_SG    = OFF_G     + (size_t)B_ * CL_;
constexpr size_t OFF_SL    = OFF_SG    + (size_t)B_ * L_ * L_;
constexpr size_t OFF_GBAR  = OFF_SL    + (size_t)B_ * L_ * L_;
constexpr size_t OFF_GATE  = OFF_GBAR  + (size_t)B_ * L_;
constexpr size_t OFF_GOUT  = OFF_GATE  + (size_t)B_ * L_;
constexpr size_t OFF_GOUT2 = OFF_GOUT  + (size_t)B_ * CL_;
constexpr size_t OFF_H1    = OFF_GOUT2 + (size_t)B_ * CL_;
constexpr size_t OFF_M2    = OFF_H1    + (size_t)NR_ * C_;
// bf16 regions (sizes in float units = bf16_elems/2)
constexpr size_t OFF_H1HI  = OFF_M2    + (size_t)NR_ * C_;
constexpr size_t OFF_H1LO  = OFF_H1HI  + (size_t)NR_ * C_ / 2;
constexpr size_t OFF_C1WHI = OFF_H1LO  + (size_t)NR_ * C_ / 2;
constexpr size_t OFF_C1WLO = OFF_C1WHI + (size_t)C4_ * C_ / 2;
constexpr size_t OFF_C2WHI = OFF_C1WLO + (size_t)C4_ * C_ / 2;
constexpr size_t OFF_C2WLO = OFF_C2WHI + (size_t)C_ * C4_ / 2;
constexpr size_t OFF_M1HI  = OFF_C2WLO + (size_t)C_ * C4_ / 2;
constexpr size_t OFF_M1LO  = OFF_M1HI  + (size_t)NR_ * C4_ / 2;
constexpr size_t SCRATCH_TOTAL = OFF_M1LO + (size_t)NR_ * C4_ / 2;
} // namespace

__device__ __align__(256) float d_scratch[SCRATCH_TOTAL];

// ============================================================================
// PTX helpers — sm_80-era only (mma.sync / ldmatrix / cp.async). NO tcgen05.
// ============================================================================
__device__ __forceinline__ uint32_t smem_to_u32(const void* p) {
    uint32_t a;
    asm("{ .reg .u64 t; cvta.to.shared.u64 t, %1; cvt.u32.u64 %0, t; }" : "=r"(a) : "l"(p));
    return a;
}
__device__ __forceinline__ void ldmat4(uint32_t (&r)[4], uint32_t addr) {
    asm volatile("ldmatrix.sync.aligned.m8n8.x4.shared.b16 {%0,%1,%2,%3}, [%4];"
                 : "=r"(r[0]), "=r"(r[1]), "=r"(r[2]), "=r"(r[3]) : "r"(addr));
}
__device__ __forceinline__ void mma16816(float (&d)[4], const uint32_t (&a)[4], const uint32_t b0, const uint32_t b1) {
    asm volatile("mma.sync.aligned.m16n8k16.row.col.f32.bf16.bf16.f32 "
                 "{%0,%1,%2,%3}, {%4,%5,%6,%7}, {%8,%9}, {%0,%1,%2,%3};"
                 : "+f"(d[0]), "+f"(d[1]), "+f"(d[2]), "+f"(d[3])
                 : "r"(a[0]), "r"(a[1]), "r"(a[2]), "r"(a[3]), "r"(b0), "r"(b1));
}
__device__ __forceinline__ void cp16(uint32_t saddr, const void* g) {
    asm volatile("cp.async.cg.shared.global [%0], [%1], 16;" :: "r"(saddr), "l"(g));
}
#define CP_COMMIT() asm volatile("cp.async.commit_group;" ::: "memory")
#define CP_WAIT1()  asm volatile("cp.async.wait_group 1;" ::: "memory")
#define CP_WAIT0()  asm volatile("cp.async.wait_group 0;" ::: "memory")

namespace {

// ---------------- reduction helpers ----------------
__device__ __forceinline__ float warpSum(float v) {
#pragma unroll
    for (int o = 16; o; o >>= 1) v += __shfl_xor_sync(0xffffffffu, v, o);
    return v;
}
__device__ __forceinline__ float warpMax(float v) {
#pragma unroll
    for (int o = 16; o; o >>= 1) v = fmaxf(v, __shfl_xor_sync(0xffffffffu, v, o));
    return v;
}
__device__ __forceinline__ float mishf(float v) {
    float sp = fmaxf(v, 0.f) + log1pf(__expf(-fabsf(v)));
    return v * tanhf(sp);
}

// ============================================================================
// fp32 SIMT GEMM (64x64x16) — attention-side GEMMs (unchanged, known good).
// ============================================================================
template <int AMODE, int BMODE>
__global__ void __launch_bounds__(256) gemm64(
    const float* __restrict__ A, const float* __restrict__ Bm, float* __restrict__ Y,
    int M, int N, int K, int lda, int ldb, int ldy,
    size_t sA, size_t sB, size_t sY,
    const float* __restrict__ biasM, const float* __restrict__ biasN,
    float scale, int act)
{
    __shared__ float As[16][64];
    __shared__ float Bs[16][64];
    A  += (size_t)blockIdx.z * sA;
    Bm += (size_t)blockIdx.z * sB;
    Y  += (size_t)blockIdx.z * sY;
    const int m0 = blockIdx.y * 64, n0 = blockIdx.x * 64;
    const int tid = threadIdx.x;
    const int ty = tid >> 4, tx = tid & 15;
    const int ra = ty * 4, cb = tx * 4;

    float acc[4][4];
#pragma unroll
    for (int i = 0; i < 4; i++)
#pragma unroll
        for (int j = 0; j < 4; j++) acc[i][j] = 0.f;

    for (int k0 = 0; k0 < K; k0 += 16) {
        if (AMODE == 0) {
            int ml = tid >> 2, kl = (tid & 3) * 4;
            float4 v = *(const float4*)(A + (size_t)(m0 + ml) * lda + k0 + kl);
            As[kl + 0][ml] = v.x; As[kl + 1][ml] = v.y;
            As[kl + 2][ml] = v.z; As[kl + 3][ml] = v.w;
        } else {
            int k = tid >> 4, ml = (tid & 15) * 4;
            *(float4*)(&As[k][ml]) = *(const float4*)(A + (size_t)(k0 + k) * lda + m0 + ml);
        }
        if (BMODE == 0) {
            int nl = tid >> 2, kl = (tid & 3) * 4;
            float4 v = *(const float4*)(Bm + (size_t)(n0 + nl) * ldb + k0 + kl);
            Bs[kl + 0][nl] = v.x; Bs[kl + 1][nl] = v.y;
            Bs[kl + 2][nl] = v.z; Bs[kl + 3][nl] = v.w;
        } else {
            int k = tid >> 4, nl = (tid & 15) * 4;
            *(float4*)(&Bs[k][nl]) = *(const float4*)(Bm + (size_t)(k0 + k) * ldb + n0 + nl);
        }
        __syncthreads();
#pragma unroll
        for (int k = 0; k < 16; k++) {
            float4 a = *(const float4*)&As[k][ra];
            float4 b = *(const float4*)&Bs[k][cb];
            const float av[4] = {a.x, a.y, a.z, a.w};
            const float bv[4] = {b.x, b.y, b.z, b.w};
#pragma unroll
            for (int i = 0; i < 4; i++)
#pragma unroll
                for (int j = 0; j < 4; j++)
                    acc[i][j] = fmaf(av[i], bv[j], acc[i][j]);
        }
        __syncthreads();
    }

#pragma unroll
    for (int i = 0; i < 4; i++) {
        int m = m0 + ra + i;
        float bmv = biasM ? biasM[m] : 0.f;
        int n = n0 + cb;
        float4 o;
        float* po = &o.x;
#pragma unroll
        for (int j = 0; j < 4; j++) {
            float v = acc[i][j] * scale + bmv;
            if (biasN) v += biasN[n + j];
            po[j] = (act == 1) ? mishf(v) : v;
        }
        *(float4*)(Y + (size_t)m * ldy + n) = o;
    }
}

// ============================================================================
// bf16-split tensor-core GEMM via mma.sync (HMMA), NT layout:
//   A: [Mtot,K] K-contig bf16 hi/lo ;  B: [Ntot,K] K-contig bf16 hi/lo
//   D = Ahi·Bhi^T + Ahi·Blo^T + Alo·Bhi^T  (fp32 accum)
// Tile: BM=128 x BN x BK=32, 8 warps (2 in M x 4 in N), warp tile 64 x BN/4.
// Two-stage cp.async pipeline. Padded 80B SMEM row stride (conflict-free
// ldmatrix: row addrs {0,80,32,112,64,16,96,48} mod 128 all distinct).
// EPI 0: outF = D + biasN (fp32).  EPI 1: mish(D+biasN) -> outHi/outLo bf16.
// ============================================================================
template <int BN, int EPI>
__global__ void __launch_bounds__(256) gemm_mma(
    const __nv_bfloat16* __restrict__ Ahi, const __nv_bfloat16* __restrict__ Alo,
    const __nv_bfloat16* __restrict__ Bhi, const __nv_bfloat16* __restrict__ Blo,
    const float* __restrict__ biasN,
    float* __restrict__ outF,
    __nv_bfloat16* __restrict__ outHi, __nv_bfloat16* __restrict__ outLo,
    int K, int ldOut)
{
    constexpr int BM = 128, BK = 32;
    constexpr int SROW = 80;                 // bytes per SMEM row (64 data + 16 pad)
    constexpr int ATILE = BM * SROW;         // 10240
    constexpr int BTILE = BN * SROW;
    constexpr int STAGE = 2 * ATILE + 2 * BTILE;
    constexpr int WN = BN / 4;               // warp N extent (32 or 16)
    constexpr int NFRAG = WN / 8;            // n8 frags per warp (4 or 2)

    extern __shared__ char smem[];
    const uint32_t sb = smem_to_u32(smem);
    const int tid = threadIdx.x, lane = tid & 31, wid = tid >> 5;
    const int wm = wid & 1, wn = wid >> 1;   // 2 x 4 warp grid
    const int m0 = blockIdx.y * BM, n0 = blockIdx.x * BN;

    float acc[4][NFRAG][4];
#pragma unroll
    for (int i = 0; i < 4; i++)
#pragma unroll
        for (int j = 0; j < NFRAG; j++)
#pragma unroll
            for (int q = 0; q < 4; q++) acc[i][j][q] = 0.f;

    auto load_stage = [&](int ch, int st) {
        const int k0 = ch * BK;
        const uint32_t base = sb + st * STAGE;
#pragma unroll
        for (int c = tid; c < BM * 4; c += 256) {          // 2 iters
            int r = c >> 2, cc = c & 3;
            size_t go = (size_t)(m0 + r) * K + k0 + cc * 8;
            uint32_t so = base + r * SROW + cc * 16;
            cp16(so, Ahi + go);
            cp16(so + ATILE, Alo + go);
        }
#pragma unroll
        for (int c = tid; c < BN * 4; c += 256) {
            int r = c >> 2, cc = c & 3;
            size_t go = (size_t)(n0 + r) * K + k0 + cc * 8;
            uint32_t so = base + 2 * ATILE + r * SROW + cc * 16;
            cp16(so, Bhi + go);
            cp16(so + BTILE, Blo + go);
        }
        CP_COMMIT();
    };

    const int nch = K / BK;
    load_stage(0, 0);
    for (int ch = 0; ch < nch; ch++) {
        const int st = ch & 1;
        if (ch + 1 < nch) { load_stage(ch + 1, st ^ 1); CP_WAIT1(); }
        else              { CP_WAIT0(); }
        __syncthreads();

        const uint32_t aBase = sb + st * STAGE;
        const uint32_t bBase = aBase + 2 * ATILE;
#pragma unroll
        for (int ks = 0; ks < 2; ks++) {
            const uint32_t colOff = (uint32_t)(ks * 2 + (lane >> 4)) * 16;
            uint32_t a_hi[4][4], a_lo[4][4];
#pragma unroll
            for (int mi = 0; mi < 4; mi++) {
                uint32_t addr = aBase + (uint32_t)(wm * 64 + mi * 16 + (lane & 15)) * SROW + colOff;
                ldmat4(a_hi[mi], addr);
                ldmat4(a_lo[mi], addr + ATILE);
            }
#pragma unroll
            for (int nt = 0; nt < NFRAG / 2; nt++) {
                uint32_t addr = bBase + (uint32_t)(wn * WN + nt * 16 + (lane & 15)) * SROW + colOff;
                uint32_t bh[4], bl[4];
                ldmat4(bh, addr);
                ldmat4(bl, addr + BTILE);
#pragma unroll
                for (int half = 0; half < 2; half++) {
                    const int ni = nt * 2 + half;
#pragma unroll
                    for (int mi = 0; mi < 4; mi++) {
                        mma16816(acc[mi][ni], a_hi[mi], bh[half], bh[2 + half]);
                        mma16816(acc[mi][ni], a_hi[mi], bl[half], bl[2 + half]);
                        mma16816(acc[mi][ni], a_lo[mi], bh[half], bh[2 + half]);
                    }
                }
            }
        }
        __syncthreads();   // guard stage reuse by the next prefetch
    }

    // ---------------- epilogue ----------------
    const int g = lane >> 2, tg = lane & 3;
#pragma unroll
    for (int mi = 0; mi < 4; mi++) {
#pragma unroll
        for (int ni = 0; ni < NFRAG; ni++) {
            const int col = n0 + wn * WN + ni * 8 + tg * 2;
            const float b0 = biasN[col], b1 = biasN[col + 1];
#pragma unroll
            for (int h = 0; h < 2; h++) {
                const int row = m0 + wm * 64 + mi * 16 + g + h * 8;
                float v0 = acc[mi][ni][h * 2 + 0] + b0;
                float v1 = acc[mi][ni][h * 2 + 1] + b1;
                const size_t o = (size_t)row * ldOut + col;
                if (EPI == 1) {
                    v0 = mishf(v0); v1 = mishf(v1);
                    __nv_bfloat16 h0 = __float2bfloat16(v0);
                    __nv_bfloat16 h1 = __float2bfloat16(v1);
                    __nv_bfloat162 hp; hp.x = h0; hp.y = h1;
                    __nv_bfloat162 lp;
                    lp.x = __float2bfloat16(v0 - __bfloat162float(h0));
                    lp.y = __float2bfloat16(v1 - __bfloat162float(h1));
                    *(__nv_bfloat162*)(outHi + o) = hp;
                    *(__nv_bfloat162*)(outLo + o) = lp;
                } else {
                    float2 fp; fp.x = v0; fp.y = v1;
                    *(float2*)(outF + o) = fp;
                }
            }
        }
    }
}

// ============================================================================
// fp32 -> bf16 hi/lo split (weights)
// ============================================================================
__global__ void split_kernel(const float* __restrict__ src,
                             __nv_bfloat16* __restrict__ hi,
                             __nv_bfloat16* __restrict__ lo, int n)
{
    int i = blockIdx.x * 256 + threadIdx.x;
    if (i < n) {
        float v = src[i];
        __nv_bfloat16 h = __float2bfloat16(v);
        hi[i] = h;
        lo[i] = __float2bfloat16(v - __bfloat162float(h));
    }
}

// ============================================================================
// gbar[b,m] = mean_c g[b,c,m]
// ============================================================================
__global__ void gbar_kernel(const float* __restrict__ g, float* __restrict__ gbar)
{
    int b = blockIdx.x, m = threadIdx.x;
    const float* p = g + (size_t)b * CL_ + m;
    float s = 0.f;
#pragma unroll 8
    for (int c = 0; c < C_; c++) s += p[(size_t)c * L_];
    gbar[b * L_ + m] = s * (1.f / C_);
}

// ============================================================================
// Row softmax over last dim (256), in place
// ============================================================================
__global__ void softmax256(float* __restrict__ S)
{
    __shared__ float sm[16];
    int row = blockIdx.x, tid = threadIdx.x;
    int lane = tid & 31, w = tid >> 5;
    float v = S[(size_t)row * L_ + tid];
    float m = warpMax(v);
    if (lane == 0) sm[w] = m;
    __syncthreads();
    float M = -1e30f;
#pragma unroll
    for (int i = 0; i < 8; i++) M = fmaxf(M, sm[i]);
    float e = __expf(v - M);
    float s = warpSum(e);
    if (lane == 0) sm[8 + w] = s;
    __syncthreads();
    float T = 0.f;
#pragma unroll
    for (int i = 0; i < 8; i++) T += sm[8 + i];
    S[(size_t)row * L_ + tid] = e / T;
}

// ============================================================================
// Local attention gate (banded softmax; zeros participate)
// ============================================================================
__global__ void local_gate_kernel(const float* __restrict__ Sl,
                                  const float* __restrict__ gbar,
                                  const float* __restrict__ wlw,
                                  const float* __restrict__ wlb,
                                  float* __restrict__ gate)
{
    int b = blockIdx.y;
    int l = blockIdx.x * 4 + (threadIdx.x >> 5);
    int lane = threadIdx.x & 31;
    const float* srow = Sl + ((size_t)b * L_ + l) * L_;
    const float* gb = gbar + (size_t)b * L_;

    int m0 = l + lane - 32;
    int m1 = l + lane;
    bool v0 = (m0 >= 0) && (m0 < L_);
    bool v1 = (m1 >= 0) && (m1 < L_);
    float s0 = v0 ? srow[m0] : 0.f;
    float s1 = v1 ? srow[m1] : 0.f;
    float g0 = v0 ? gb[m0] : 0.f;
    float g1 = v1 ? gb[m1] : 0.f;

    float mx = warpMax(fmaxf(s0, s1));
    float e0 = __expf(s0 - mx), e1 = __expf(s1 - mx);
    float num = warpSum(e0 * g0 + e1 * g1);
    float den = warpSum(e0 + e1);
    if (lane == 0) {
        float pooled = num / den;
        float z = wlw[0] * pooled + wlb[0];
        gate[b * L_ + l] = 1.f / (1.f + __expf(-z));
    }
}

// ============================================================================
// LN1: h = gout2*gate + x; write h1 fp32 AND bf16 hi/lo (row = l*B+b, [*,C])
// ============================================================================
__global__ void ln1_kernel(const float* __restrict__ gout2,
                           const float* __restrict__ gate,
                           const float* __restrict__ x,
                           const float* __restrict__ g1, const float* __restrict__ b1,
                           float* __restrict__ h1,
                           __nv_bfloat16* __restrict__ h1hi,
                           __nv_bfloat16* __restrict__ h1lo)
{
    __shared__ float sm[16];
    int l = blockIdx.x, b = blockIdx.y, tid = threadIdx.x;
    int lane = tid & 31, w = tid >> 5;
    float gt = gate[b * L_ + l];
    size_t base = (size_t)b * CL_ + l;
    float v0 = fmaf(gout2[base + (size_t)tid * L_], gt, x[base + (size_t)tid * L_]);
    float v1 = fmaf(gout2[base + (size_t)(tid + 256) * L_], gt, x[base + (size_t)(tid + 256) * L_]);
    float s = warpSum(v0 + v1);
    float q = warpSum(v0 * v0 + v1 * v1);
    if (lane == 0) { sm[w] = s; sm[8 + w] = q; }
    __syncthreads();
    float S = 0.f, Q = 0.f;
#pragma unroll
    for (int i = 0; i < 8; i++) { S += sm[i]; Q += sm[8 + i]; }
    float mean = S * (1.f / C_);
    float var = Q * (1.f / C_) - mean * mean;
    float r = rsqrtf(var + 1e-5f);
    size_t o = ((size_t)l * B_ + b) * C_;
    float y0 = (v0 - mean) * r * g1[tid] + b1[tid];
    float y1 = (v1 - mean) * r * g1[tid + 256] + b1[tid + 256];
    h1[o + tid] = y0;
    h1[o + tid + 256] = y1;
    __nv_bfloat16 h0b = __float2bfloat16(y0);
    __nv_bfloat16 h1b = __float2bfloat16(y1);
    h1hi[o + tid] = h0b;
    h1hi[o + tid + 256] = h1b;
    h1lo[o + tid] = __float2bfloat16(y0 - __bfloat162float(h0b));
    h1lo[o + tid + 256] = __float2bfloat16(y1 - __bfloat162float(h1b));
}

// ============================================================================
// LN2 + output transpose
// ============================================================================
__global__ void ln2_kernel(const float* __restrict__ m2,
                           const float* __restrict__ h1,
                           const float* __restrict__ g2, const float* __restrict__ b2,
                           float* __restrict__ out)
{
    __shared__ float sm[16];
    int row = blockIdx.x, tid = threadIdx.x;
    int lane = tid & 31, w = tid >> 5;
    int l = row / B_, b = row % B_;
    size_t base = (size_t)row * C_;
    float v0 = m2[base + tid] + h1[base + tid];
    float v1 = m2[base + tid + 256] + h1[base + tid + 256];
    float s = warpSum(v0 + v1);
    float q = warpSum(v0 * v0 + v1 * v1);
    if (lane == 0) { sm[w] = s; sm[8 + w] = q; }
    __syncthreads();
    float S = 0.f, Q = 0.f;
#pragma unroll
    for (int i = 0; i < 8; i++) { S += sm[i]; Q += sm[8 + i]; }
    float mean = S * (1.f / C_);
    float var = Q * (1.f / C_) - mean * mean;
    float r = rsqrtf(var + 1e-5f);
    size_t ob = (size_t)b * CL_ + l;
    out[ob + (size_t)tid * L_]         = (v0 - mean) * r * g2[tid] + b2[tid];
    out[ob + (size_t)(tid + 256) * L_] = (v1 - mean) * r * g2[tid + 256] + b2[tid + 256];
}

} // namespace

// ============================================================================
// Host launcher
// ============================================================================
extern "C" void kernel_launch(void* const* d_in, const int* in_sizes, int n_in,
                              void* d_out, int out_size)
{
    (void)in_sizes; (void)n_in; (void)out_size;
    float* scratch = nullptr;
    cudaGetSymbolAddress((void**)&scratch, d_scratch);

    const float* x       = (const float*)d_in[0];
    const float* theta_w = (const float*)d_in[1];
    const float* theta_b = (const float*)d_in[2];
    const float* phi_w   = (const float*)d_in[3];
    const float* phi_b   = (const float*)d_in[4];
    const float* g_w     = (const float*)d_in[5];
    const float* g_b     = (const float*)d_in[6];
    const float* wl_w    = (const float*)d_in[7];
    const float* wl_b    = (const float*)d_in[8];
    const float* wg_w    = (const float*)d_in[9];
    const float* wg_b    = (const float*)d_in[10];
    const float* conv1_w = (const float*)d_in[11];
    const float* conv1_b = (const float*)d_in[12];
    const float* conv2_w = (const float*)d_in[13];
    const float* conv2_b = (const float*)d_in[14];
    const float* ln1_g   = (const float*)d_in[15];
    const float* ln1_b   = (const float*)d_in[16];
    const float* ln2_g   = (const float*)d_in[17];
    const float* ln2_b   = (const float*)d_in[18];
    float* out = (float*)d_out;

    float* th    = scratch + OFF_THETA;
    float* ph    = scratch + OFF_PHI;
    float* gg    = scratch + OFF_G;
    float* Sg    = scratch + OFF_SG;
    float* Sl    = scratch + OFF_SL;
    float* gbar  = scratch + OFF_GBAR;
    float* gate  = scratch + OFF_GATE;
    float* gout  = scratch + OFF_GOUT;
    float* gout2 = scratch + OFF_GOUT2;
    float* h1    = scratch + OFF_H1;
    float* m2    = scratch + OFF_M2;
    __nv_bfloat16* h1hi  = (__nv_bfloat16*)(scratch + OFF_H1HI);
    __nv_bfloat16* h1lo  = (__nv_bfloat16*)(scratch + OFF_H1LO);
    __nv_bfloat16* c1whi = (__nv_bfloat16*)(scratch + OFF_C1WHI);
    __nv_bfloat16* c1wlo = (__nv_bfloat16*)(scratch + OFF_C1WLO);
    __nv_bfloat16* c2whi = (__nv_bfloat16*)(scratch + OFF_C2WHI);
    __nv_bfloat16* c2wlo = (__nv_bfloat16*)(scratch + OFF_C2WLO);
    __nv_bfloat16* m1hi  = (__nv_bfloat16*)(scratch + OFF_M1HI);
    __nv_bfloat16* m1lo  = (__nv_bfloat16*)(scratch + OFF_M1LO);

    // SMEM: BN=128 stage = 4*10240 = 40960 (x2 = 81920); BN=64 stage = 30720 (x2 = 61440)
    constexpr int SMEM_MLP1 = 81920;
    constexpr int SMEM_MLP2 = 61440;
    cudaFuncSetAttribute(gemm_mma<128, 1>, cudaFuncAttributeMaxDynamicSharedMemorySize, SMEM_MLP1);
    cudaFuncSetAttribute(gemm_mma<64, 0>,  cudaFuncAttributeMaxDynamicSharedMemorySize, SMEM_MLP2);

    // 0) split MLP weights to bf16 hi/lo
    split_kernel<<<(C4_ * C_ + 255) / 256, 256>>>(conv1_w, c1whi, c1wlo, C4_ * C_);
    split_kernel<<<(C_ * C4_ + 255) / 256, 256>>>(conv2_w, c2whi, c2wlo, C_ * C4_);

    // 1-3) theta/phi/g = W @ x + b
    {
        dim3 grid(L_ / 64, C_ / 64, B_);
        gemm64<0, 1><<<grid, 256>>>(theta_w, x, th, C_, L_, C_, C_, L_, L_,
                                    0, CL_, CL_, theta_b, nullptr, 1.f, 0);
        gemm64<0, 1><<<grid, 256>>>(phi_w, x, ph, C_, L_, C_, C_, L_, L_,
                                    0, CL_, CL_, phi_b, nullptr, 1.f, 0);
        gemm64<0, 1><<<grid, 256>>>(g_w, x, gg, C_, L_, C_, C_, L_, L_,
                                    0, CL_, CL_, g_b, nullptr, 1.f, 0);
    }

    // 4-5) Sg = scale*phi^T@theta, Sl = scale*phi^T@g
    {
        dim3 grid(L_ / 64, L_ / 64, B_);
        gemm64<1, 1><<<grid, 256>>>(ph, th, Sg, L_, L_, C_, L_, L_, L_,
                                    CL_, CL_, (size_t)L_ * L_, nullptr, nullptr, SCALE_, 0);
        gemm64<1, 1><<<grid, 256>>>(ph, gg, Sl, L_, L_, C_, L_, L_, L_,
                                    CL_, CL_, (size_t)L_ * L_, nullptr, nullptr, SCALE_, 0);
    }

    // 6) gbar ; 7) softmax(Sg) ; 8) local gate
    gbar_kernel<<<B_, L_>>>(gg, gbar);
    softmax256<<<B_ * L_, 256>>>(Sg);
    {
        dim3 grid(L_ / 4, B_);
        local_gate_kernel<<<grid, 128>>>(Sl, gbar, wl_w, wl_b, gate);
    }

    // 9) gout = g @ gp^T ; 10) gout2 = wg_w @ gout + wg_b
    {
        dim3 grid(L_ / 64, C_ / 64, B_);
        gemm64<0, 0><<<grid, 256>>>(gg, Sg, gout, C_, L_, L_, L_, L_, L_,
                                    CL_, (size_t)L_ * L_, CL_, nullptr, nullptr, 1.f, 0);
        gemm64<0, 1><<<grid, 256>>>(wg_w, gout, gout2, C_, L_, C_, C_, L_, L_,
                                    0, CL_, CL_, wg_b, nullptr, 1.f, 0);
    }

    // 11) h1 = LN1(gout2*gate + x)  (+ bf16 hi/lo split)
    {
        dim3 grid(L_, B_);
        ln1_kernel<<<grid, 256>>>(gout2, gate, x, ln1_g, ln1_b, h1, h1hi, h1lo);
    }

    // 12) m1 = Mish(h1 @ conv1_w^T + conv1_b) -> bf16 hi/lo   [mma.sync]
    {
        dim3 grid(C4_ / 128, NR_ / 128);
        gemm_mma<128, 1><<<grid, 256, SMEM_MLP1>>>(h1hi, h1lo, c1whi, c1wlo, conv1_b,
                                                   nullptr, m1hi, m1lo, C_, C4_);
    }

    // 13) m2 = m1 @ conv2_w^T + conv2_b -> fp32   [mma.sync]
    {
        dim3 grid(C_ / 64, NR_ / 128);
        gemm_mma<64, 0><<<grid, 256, SMEM_MLP2>>>(m1hi, m1lo, c2whi, c2wlo, conv2_b,
                                                  m2, nullptr, nullptr, C4_, C_);
    }

    // 14) out = LN2(m2 + h1), transposed to [B,C,L]
    ln2_kernel<<<NR_, 256>>>(m2, h1, ln2_g, ln2_b, out);
}

// round 5
// speedup vs baseline: 1.9468x; 1.4664x over previous
#include <cuda_runtime.h>
#include <cuda_bf16.h>
#include <math.h>
#include <stdint.h>

// ============================================================================
// Problem constants
// ============================================================================
namespace {
constexpr int B_ = 8, C_ = 512, L_ = 256;
constexpr int CL_ = C_ * L_;           // 131072
constexpr int C3_ = 3 * C_;            // 1536
constexpr int C4_ = 4 * C_;            // 2048
constexpr int NR_ = L_ * B_;           // 2048
constexpr float SCALE_ = 0.044194173824159216f; // 512^-0.5

// ---------------- scratch offsets (float units; all sizes mult of 512) -----
constexpr size_t OFF_XT_HI   = 0;                                    // bf16 [B,L,C]
constexpr size_t OFF_XT_LO   = OFF_XT_HI   + (size_t)B_ * CL_ / 2;
constexpr size_t OFF_WQKV_HI = OFF_XT_LO   + (size_t)B_ * CL_ / 2;   // bf16 [3C,C]
constexpr size_t OFF_WQKV_LO = OFF_WQKV_HI + (size_t)C3_ * C_ / 2;
constexpr size_t OFF_QKV_B   = OFF_WQKV_LO + (size_t)C3_ * C_ / 2;   // f32 [1536]
constexpr size_t OFF_WWG_HI  = OFF_QKV_B   + 1536;
constexpr size_t OFF_WWG_LO  = OFF_WWG_HI  + (size_t)C_ * C_ / 2;
constexpr size_t OFF_C1WHI   = OFF_WWG_LO  + (size_t)C_ * C_ / 2;
constexpr size_t OFF_C1WLO   = OFF_C1WHI   + (size_t)C4_ * C_ / 2;
constexpr size_t OFF_C2WHI   = OFF_C1WLO   + (size_t)C4_ * C_ / 2;
constexpr size_t OFF_C2WLO   = OFF_C2WHI   + (size_t)C_ * C4_ / 2;
constexpr size_t OFF_QKVT_HI = OFF_C2WLO   + (size_t)C_ * C4_ / 2;   // bf16 [B,L,3C]
constexpr size_t OFF_QKVT_LO = OFF_QKVT_HI + (size_t)B_ * L_ * C3_ / 2;
constexpr size_t OFF_SG      = OFF_QKVT_LO + (size_t)B_ * L_ * C3_ / 2; // f32 [B,L,L]
constexpr size_t OFF_SL      = OFF_SG      + (size_t)B_ * L_ * L_;
constexpr size_t OFF_GP_HI   = OFF_SL      + (size_t)B_ * L_ * L_;   // bf16 [B,L,L]
constexpr size_t OFF_GP_LO   = OFF_GP_HI   + (size_t)B_ * L_ * L_ / 2;
constexpr size_t OFF_GG2_HI  = OFF_GP_LO   + (size_t)B_ * L_ * L_ / 2; // bf16 [B,C,L]
constexpr size_t OFF_GG2_LO  = OFF_GG2_HI  + (size_t)B_ * CL_ / 2;
constexpr size_t OFF_GBAR    = OFF_GG2_LO  + (size_t)B_ * CL_ / 2;
constexpr size_t OFF_GATE    = OFF_GBAR    + (size_t)B_ * L_;
constexpr size_t OFF_GOUTT_HI= OFF_GATE    + (size_t)B_ * L_;        // bf16 [B,L,C]
constexpr size_t OFF_GOUTT_LO= OFF_GOUTT_HI+ (size_t)B_ * CL_ / 2;
constexpr size_t OFF_GOUT2T  = OFF_GOUTT_LO+ (size_t)B_ * CL_ / 2;   // f32 [B,L,C]
constexpr size_t OFF_H1      = OFF_GOUT2T  + (size_t)B_ * CL_;       // f32 [NR,C]
constexpr size_t OFF_H1HI    = OFF_H1      + (size_t)NR_ * C_;
constexpr size_t OFF_H1LO    = OFF_H1HI    + (size_t)NR_ * C_ / 2;
constexpr size_t OFF_M1HI    = OFF_H1LO    + (size_t)NR_ * C_ / 2;   // bf16 [NR,C4]
constexpr size_t OFF_M1LO    = OFF_M1HI    + (size_t)NR_ * C4_ / 2;
constexpr size_t OFF_M2      = OFF_M1LO    + (size_t)NR_ * C4_ / 2;  // f32 [NR,C]
constexpr size_t SCRATCH_TOTAL = OFF_M2    + (size_t)NR_ * C_;
} // namespace

__device__ __align__(256) float d_scratch[SCRATCH_TOTAL];

// ============================================================================
// PTX helpers — sm_80-era only (mma.sync / ldmatrix / cp.async).
// ============================================================================
__device__ __forceinline__ uint32_t smem_to_u32(const void* p) {
    uint32_t a;
    asm("{ .reg .u64 t; cvta.to.shared.u64 t, %1; cvt.u32.u64 %0, t; }" : "=r"(a) : "l"(p));
    return a;
}
__device__ __forceinline__ void ldmat4(uint32_t (&r)[4], uint32_t addr) {
    asm volatile("ldmatrix.sync.aligned.m8n8.x4.shared.b16 {%0,%1,%2,%3}, [%4];"
                 : "=r"(r[0]), "=r"(r[1]), "=r"(r[2]), "=r"(r[3]) : "r"(addr));
}
__device__ __forceinline__ void mma16816(float (&d)[4], const uint32_t (&a)[4], const uint32_t b0, const uint32_t b1) {
    asm volatile("mma.sync.aligned.m16n8k16.row.col.f32.bf16.bf16.f32 "
                 "{%0,%1,%2,%3}, {%4,%5,%6,%7}, {%8,%9}, {%0,%1,%2,%3};"
                 : "+f"(d[0]), "+f"(d[1]), "+f"(d[2]), "+f"(d[3])
                 : "r"(a[0]), "r"(a[1]), "r"(a[2]), "r"(a[3]), "r"(b0), "r"(b1));
}
__device__ __forceinline__ void cp16(uint32_t saddr, const void* g) {
    asm volatile("cp.async.cg.shared.global [%0], [%1], 16;" :: "r"(saddr), "l"(g));
}
#define CP_COMMIT() asm volatile("cp.async.commit_group;" ::: "memory")
#define CP_WAIT1()  asm volatile("cp.async.wait_group 1;" ::: "memory")
#define CP_WAIT0()  asm volatile("cp.async.wait_group 0;" ::: "memory")

namespace {

__device__ __forceinline__ float warpSum(float v) {
#pragma unroll
    for (int o = 16; o; o >>= 1) v += __shfl_xor_sync(0xffffffffu, v, o);
    return v;
}
__device__ __forceinline__ float warpMax(float v) {
#pragma unroll
    for (int o = 16; o; o >>= 1) v = fmaxf(v, __shfl_xor_sync(0xffffffffu, v, o));
    return v;
}
__device__ __forceinline__ float mishf(float v) {
    float sp = fmaxf(v, 0.f) + log1pf(__expf(-fabsf(v)));
    return v * tanhf(sp);
}

// ============================================================================
// bf16-split tensor-core GEMM (validated in R4), generalized with leading
// dims + batch strides.  NT layout:
//   A: [M,K] K-contig (lda) hi/lo ;  B: [N,K] K-contig (ldb) hi/lo
//   D = Ahi·Bhi^T + Ahi·Blo^T + Alo·Bhi^T, fp32 accum
//   v = scale*D (+ biasN); ACT -> mish; OUTFMT 0: fp32 out; 1: bf16 hi/lo out
// ============================================================================
template <int BN, int OUTFMT, int ACT>
__global__ void __launch_bounds__(256) gemm_mma(
    const __nv_bfloat16* __restrict__ Ahi, const __nv_bfloat16* __restrict__ Alo,
    const __nv_bfloat16* __restrict__ Bhi, const __nv_bfloat16* __restrict__ Blo,
    const float* __restrict__ biasN,
    float* __restrict__ outF,
    __nv_bfloat16* __restrict__ outHi, __nv_bfloat16* __restrict__ outLo,
    int K, int lda, int ldb, int ldOut,
    size_t sA, size_t sB, size_t sO, float scale)
{
    constexpr int BM = 128, BK = 32;
    constexpr int SROW = 80;
    constexpr int ATILE = BM * SROW;         // 10240
    constexpr int BTILE = BN * SROW;
    constexpr int STAGE = 2 * ATILE + 2 * BTILE;
    constexpr int WN = BN / 4;
    constexpr int NFRAG = WN / 8;

    extern __shared__ char smem[];
    const uint32_t sb = smem_to_u32(smem);
    const int tid = threadIdx.x, lane = tid & 31, wid = tid >> 5;
    const int wm = wid & 1, wn = wid >> 1;
    const int m0 = blockIdx.y * BM, n0 = blockIdx.x * BN;
    const int z = blockIdx.z;

    Ahi += (size_t)z * sA; Alo += (size_t)z * sA;
    Bhi += (size_t)z * sB; Blo += (size_t)z * sB;
    if (OUTFMT == 0) outF += (size_t)z * sO;
    else { outHi += (size_t)z * sO; outLo += (size_t)z * sO; }

    float acc[4][NFRAG][4];
#pragma unroll
    for (int i = 0; i < 4; i++)
#pragma unroll
        for (int j = 0; j < NFRAG; j++)
#pragma unroll
            for (int q = 0; q < 4; q++) acc[i][j][q] = 0.f;

    auto load_stage = [&](int ch, int st) {
        const int k0 = ch * BK;
        const uint32_t base = sb + st * STAGE;
#pragma unroll
        for (int c = tid; c < BM * 4; c += 256) {
            int r = c >> 2, cc = c & 3;
            size_t go = (size_t)(m0 + r) * lda + k0 + cc * 8;
            uint32_t so = base + r * SROW + cc * 16;
            cp16(so, Ahi + go);
            cp16(so + ATILE, Alo + go);
        }
#pragma unroll
        for (int c = tid; c < BN * 4; c += 256) {
            int r = c >> 2, cc = c & 3;
            size_t go = (size_t)(n0 + r) * ldb + k0 + cc * 8;
            uint32_t so = base + 2 * ATILE + r * SROW + cc * 16;
            cp16(so, Bhi + go);
            cp16(so + BTILE, Blo + go);
        }
        CP_COMMIT();
    };

    const int nch = K / BK;
    load_stage(0, 0);
    for (int ch = 0; ch < nch; ch++) {
        const int st = ch & 1;
        if (ch + 1 < nch) { load_stage(ch + 1, st ^ 1); CP_WAIT1(); }
        else              { CP_WAIT0(); }
        __syncthreads();

        const uint32_t aBase = sb + st * STAGE;
        const uint32_t bBase = aBase + 2 * ATILE;
#pragma unroll
        for (int ks = 0; ks < 2; ks++) {
            const uint32_t colOff = (uint32_t)(ks * 2 + (lane >> 4)) * 16;
            uint32_t a_hi[4][4], a_lo[4][4];
#pragma unroll
            for (int mi = 0; mi < 4; mi++) {
                uint32_t addr = aBase + (uint32_t)(wm * 64 + mi * 16 + (lane & 15)) * SROW + colOff;
                ldmat4(a_hi[mi], addr);
                ldmat4(a_lo[mi], addr + ATILE);
            }
#pragma unroll
            for (int nt = 0; nt < NFRAG / 2; nt++) {
                uint32_t addr = bBase + (uint32_t)(wn * WN + nt * 16 + (lane & 15)) * SROW + colOff;
                uint32_t bh[4], bl[4];
                ldmat4(bh, addr);
                ldmat4(bl, addr + BTILE);
#pragma unroll
                for (int half = 0; half < 2; half++) {
                    const int ni = nt * 2 + half;
#pragma unroll
                    for (int mi = 0; mi < 4; mi++) {
                        mma16816(acc[mi][ni], a_hi[mi], bh[half], bh[2 + half]);
                        mma16816(acc[mi][ni], a_hi[mi], bl[half], bl[2 + half]);
                        mma16816(acc[mi][ni], a_lo[mi], bh[half], bh[2 + half]);
                    }
                }
            }
        }
        __syncthreads();
    }

    // ---------------- epilogue ----------------
    const int g = lane >> 2, tg = lane & 3;
#pragma unroll
    for (int mi = 0; mi < 4; mi++) {
#pragma unroll
        for (int ni = 0; ni < NFRAG; ni++) {
            const int col = n0 + wn * WN + ni * 8 + tg * 2;
            const float b0 = biasN ? biasN[col] : 0.f;
            const float b1 = biasN ? biasN[col + 1] : 0.f;
#pragma unroll
            for (int h = 0; h < 2; h++) {
                const int row = m0 + wm * 64 + mi * 16 + g + h * 8;
                float v0 = acc[mi][ni][h * 2 + 0] * scale + b0;
                float v1 = acc[mi][ni][h * 2 + 1] * scale + b1;
                if (ACT == 1) { v0 = mishf(v0); v1 = mishf(v1); }
                const size_t o = (size_t)row * ldOut + col;
                if (OUTFMT == 1) {
                    __nv_bfloat16 h0 = __float2bfloat16(v0);
                    __nv_bfloat16 h1 = __float2bfloat16(v1);
                    __nv_bfloat162 hp; hp.x = h0; hp.y = h1;
                    __nv_bfloat162 lp;
                    lp.x = __float2bfloat16(v0 - __bfloat162float(h0));
                    lp.y = __float2bfloat16(v1 - __bfloat162float(h1));
                    *(__nv_bfloat162*)(outHi + o) = hp;
                    *(__nv_bfloat162*)(outLo + o) = lp;
                } else {
                    float2 fp; fp.x = v0; fp.y = v1;
                    *(float2*)(outF + o) = fp;
                }
            }
        }
    }
}

// ============================================================================
// fp32 -> bf16 hi/lo split (weights)
// ============================================================================
__global__ void split_kernel(const float* __restrict__ src,
                             __nv_bfloat16* __restrict__ hi,
                             __nv_bfloat16* __restrict__ lo, int n)
{
    int i = blockIdx.x * 256 + threadIdx.x;
    if (i < n) {
        float v = src[i];
        __nv_bfloat16 h = __float2bfloat16(v);
        hi[i] = h;
        lo[i] = __float2bfloat16(v - __bfloat162float(h));
    }
}

// concat qkv biases -> [1536]
__global__ void concat_bias(const float* __restrict__ tb, const float* __restrict__ pb,
                            const float* __restrict__ gb, float* __restrict__ out)
{
    int i = blockIdx.x * 256 + threadIdx.x;
    if (i < C_) out[i] = tb[i];
    else if (i < 2 * C_) out[i] = pb[i - C_];
    else if (i < 3 * C_) out[i] = gb[i - 2 * C_];
}

// ============================================================================
// transpose + split: x [B,C,L] f32 -> xT [B,L,C] bf16 hi/lo
// block (32,8), grid (L/32, C/32, B)
// ============================================================================
__global__ void transpose_split_x(const float* __restrict__ x,
                                  __nv_bfloat16* __restrict__ hi,
                                  __nv_bfloat16* __restrict__ lo)
{
    __shared__ float t[32][33];
    const int b = blockIdx.z;
    const int l0 = blockIdx.x * 32, c0 = blockIdx.y * 32;
    const int tx = threadIdx.x, ty = threadIdx.y;
    const float* xb = x + (size_t)b * CL_;
#pragma unroll
    for (int j = 0; j < 4; j++)
        t[ty + j * 8][tx] = xb[(size_t)(c0 + ty + j * 8) * L_ + l0 + tx];
    __syncthreads();
#pragma unroll
    for (int j = 0; j < 4; j++) {
        int l = l0 + ty + j * 8;
        float v = t[tx][ty + j * 8];
        __nv_bfloat16 h = __float2bfloat16(v);
        size_t o = ((size_t)b * L_ + l) * C_ + c0 + tx;
        hi[o] = h;
        lo[o] = __float2bfloat16(v - __bfloat162float(h));
    }
}

// ============================================================================
// transpose bf16 pair: ggT slice [B,L,(3C) cols 1024..1535] -> gg2 [B,C,L]
// block (32,8), grid (L/32, C/32, B)
// ============================================================================
__global__ void transpose_g(const __nv_bfloat16* __restrict__ inHi,
                            const __nv_bfloat16* __restrict__ inLo,
                            __nv_bfloat16* __restrict__ outHi,
                            __nv_bfloat16* __restrict__ outLo)
{
    __shared__ __nv_bfloat16 th[32][34];
    __shared__ __nv_bfloat16 tl[32][34];
    const int b = blockIdx.z;
    const int l0 = blockIdx.x * 32, c0 = blockIdx.y * 32;
    const int tx = threadIdx.x, ty = threadIdx.y;
#pragma unroll
    for (int j = 0; j < 4; j++) {
        size_t idx = ((size_t)b * L_ + l0 + ty + j * 8) * C3_ + 2 * C_ + c0 + tx;
        th[ty + j * 8][tx] = inHi[idx];
        tl[ty + j * 8][tx] = inLo[idx];
    }
    __syncthreads();
#pragma unroll
    for (int j = 0; j < 4; j++) {
        int c = c0 + ty + j * 8;
        size_t o = ((size_t)b * C_ + c) * L_ + l0 + tx;
        outHi[o] = th[tx][ty + j * 8];
        outLo[o] = tl[tx][ty + j * 8];
    }
}

// ============================================================================
// gbar[b,m] = mean_c g[b,c,m] from qkvT g-slice (rows m, cols c contiguous)
// grid (32, B), block 256 (8 warps, one m per warp)
// ============================================================================
__global__ void gbar_kernel(const __nv_bfloat16* __restrict__ gHi,
                            const __nv_bfloat16* __restrict__ gLo,
                            float* __restrict__ gbar)
{
    const int b = blockIdx.y;
    const int m = blockIdx.x * 8 + (threadIdx.x >> 5);
    const int lane = threadIdx.x & 31;
    const size_t base = ((size_t)b * L_ + m) * C3_ + 2 * C_;
    float s = 0.f;
#pragma unroll
    for (int c = lane; c < C_; c += 32)
        s += __bfloat162float(gHi[base + c]) + __bfloat162float(gLo[base + c]);
    s = warpSum(s);
    if (lane == 0) gbar[b * L_ + m] = s * (1.f / C_);
}

// ============================================================================
// Row softmax over 256, write bf16 hi/lo. One block per row.
// ============================================================================
__global__ void softmax_split(const float* __restrict__ S,
                              __nv_bfloat16* __restrict__ pHi,
                              __nv_bfloat16* __restrict__ pLo)
{
    __shared__ float sm[16];
    int row = blockIdx.x, tid = threadIdx.x;
    int lane = tid & 31, w = tid >> 5;
    float v = S[(size_t)row * L_ + tid];
    float m = warpMax(v);
    if (lane == 0) sm[w] = m;
    __syncthreads();
    float M = -1e30f;
#pragma unroll
    for (int i = 0; i < 8; i++) M = fmaxf(M, sm[i]);
    float e = __expf(v - M);
    float s = warpSum(e);
    if (lane == 0) sm[8 + w] = s;
    __syncthreads();
    float T = 0.f;
#pragma unroll
    for (int i = 0; i < 8; i++) T += sm[8 + i];
    float p = e / T;
    __nv_bfloat16 h = __float2bfloat16(p);
    size_t o = (size_t)row * L_ + tid;
    pHi[o] = h;
    pLo[o] = __float2bfloat16(p - __bfloat162float(h));
}

// ============================================================================
// Local attention gate (banded softmax over Sl; zeros participate)
// ============================================================================
__global__ void local_gate_kernel(const float* __restrict__ Sl,
                                  const float* __restrict__ gbar,
                                  const float* __restrict__ wlw,
                                  const float* __restrict__ wlb,
                                  float* __restrict__ gate)
{
    int b = blockIdx.y;
    int l = blockIdx.x * 4 + (threadIdx.x >> 5);
    int lane = threadIdx.x & 31;
    const float* srow = Sl + ((size_t)b * L_ + l) * L_;
    const float* gb = gbar + (size_t)b * L_;

    int m0 = l + lane - 32;
    int m1 = l + lane;
    bool v0 = (m0 >= 0) && (m0 < L_);
    bool v1 = (m1 >= 0) && (m1 < L_);
    float s0 = v0 ? srow[m0] : 0.f;
    float s1 = v1 ? srow[m1] : 0.f;
    float g0 = v0 ? gb[m0] : 0.f;
    float g1 = v1 ? gb[m1] : 0.f;

    float mx = warpMax(fmaxf(s0, s1));
    float e0 = __expf(s0 - mx), e1 = __expf(s1 - mx);
    float num = warpSum(e0 * g0 + e1 * g1);
    float den = warpSum(e0 + e1);
    if (lane == 0) {
        float pooled = num / den;
        float z = wlw[0] * pooled + wlb[0];
        gate[b * L_ + l] = 1.f / (1.f + __expf(-z));
    }
}

// ============================================================================
// LN1: h = gout2T*gate + x ; h1 fp32 + bf16 hi/lo at row (l*B+b), [*,C]
// gout2T [B,L,C] contiguous in c; x [B,C,L] strided.
// ============================================================================
__global__ void ln1_kernel(const float* __restrict__ gout2T,
                           const float* __restrict__ gate,
                           const float* __restrict__ x,
                           const float* __restrict__ g1, const float* __restrict__ b1,
                           float* __restrict__ h1,
                           __nv_bfloat16* __restrict__ h1hi,
                           __nv_bfloat16* __restrict__ h1lo)
{
    __shared__ float sm[16];
    int l = blockIdx.x, b = blockIdx.y, tid = threadIdx.x;
    int lane = tid & 31, w = tid >> 5;
    float gt = gate[b * L_ + l];
    size_t gbase = ((size_t)b * L_ + l) * C_;
    size_t xbase = (size_t)b * CL_ + l;
    float v0 = fmaf(gout2T[gbase + tid], gt, x[xbase + (size_t)tid * L_]);
    float v1 = fmaf(gout2T[gbase + tid + 256], gt, x[xbase + (size_t)(tid + 256) * L_]);
    float s = warpSum(v0 + v1);
    float q = warpSum(v0 * v0 + v1 * v1);
    if (lane == 0) { sm[w] = s; sm[8 + w] = q; }
    __syncthreads();
    float S = 0.f, Q = 0.f;
#pragma unroll
    for (int i = 0; i < 8; i++) { S += sm[i]; Q += sm[8 + i]; }
    float mean = S * (1.f / C_);
    float var = Q * (1.f / C_) - mean * mean;
    float r = rsqrtf(var + 1e-5f);
    size_t o = ((size_t)l * B_ + b) * C_;
    float y0 = (v0 - mean) * r * g1[tid] + b1[tid];
    float y1 = (v1 - mean) * r * g1[tid + 256] + b1[tid + 256];
    h1[o + tid] = y0;
    h1[o + tid + 256] = y1;
    __nv_bfloat16 h0b = __float2bfloat16(y0);
    __nv_bfloat16 h1b = __float2bfloat16(y1);
    h1hi[o + tid] = h0b;
    h1hi[o + tid + 256] = h1b;
    h1lo[o + tid] = __float2bfloat16(y0 - __bfloat162float(h0b));
    h1lo[o + tid + 256] = __float2bfloat16(y1 - __bfloat162float(h1b));
}

// ============================================================================
// LN2 + output transpose
// ============================================================================
__global__ void ln2_kernel(const float* __restrict__ m2,
                           const float* __restrict__ h1,
                           const float* __restrict__ g2, const float* __restrict__ b2,
                           float* __restrict__ out)
{
    __shared__ float sm[16];
    int row = blockIdx.x, tid = threadIdx.x;
    int lane = tid & 31, w = tid >> 5;
    int l = row / B_, b = row % B_;
    size_t base = (size_t)row * C_;
    float v0 = m2[base + tid] + h1[base + tid];
    float v1 = m2[base + tid + 256] + h1[base + tid + 256];
    float s = warpSum(v0 + v1);
    float q = warpSum(v0 * v0 + v1 * v1);
    if (lane == 0) { sm[w] = s; sm[8 + w] = q; }
    __syncthreads();
    float S = 0.f, Q = 0.f;
#pragma unroll
    for (int i = 0; i < 8; i++) { S += sm[i]; Q += sm[8 + i]; }
    float mean = S * (1.f / C_);
    float var = Q * (1.f / C_) - mean * mean;
    float r = rsqrtf(var + 1e-5f);
    size_t ob = (size_t)b * CL_ + l;
    out[ob + (size_t)tid * L_]         = (v0 - mean) * r * g2[tid] + b2[tid];
    out[ob + (size_t)(tid + 256) * L_] = (v1 - mean) * r * g2[tid + 256] + b2[tid + 256];
}

} // namespace

// ============================================================================
// Host launcher
// ============================================================================
extern "C" void kernel_launch(void* const* d_in, const int* in_sizes, int n_in,
                              void* d_out, int out_size)
{
    (void)in_sizes; (void)n_in; (void)out_size;
    float* scratch = nullptr;
    cudaGetSymbolAddress((void**)&scratch, d_scratch);

    const float* x       = (const float*)d_in[0];
    const float* theta_w = (const float*)d_in[1];
    const float* theta_b = (const float*)d_in[2];
    const float* phi_w   = (const float*)d_in[3];
    const float* phi_b   = (const float*)d_in[4];
    const float* g_w     = (const float*)d_in[5];
    const float* g_b     = (const float*)d_in[6];
    const float* wl_w    = (const float*)d_in[7];
    const float* wl_b    = (const float*)d_in[8];
    const float* wg_w    = (const float*)d_in[9];
    const float* wg_b    = (const float*)d_in[10];
    const float* conv1_w = (const float*)d_in[11];
    const float* conv1_b = (const float*)d_in[12];
    const float* conv2_w = (const float*)d_in[13];
    const float* conv2_b = (const float*)d_in[14];
    const float* ln1_g   = (const float*)d_in[15];
    const float* ln1_b   = (const float*)d_in[16];
    const float* ln2_g   = (const float*)d_in[17];
    const float* ln2_b   = (const float*)d_in[18];
    float* out = (float*)d_out;

    __nv_bfloat16* xtHi   = (__nv_bfloat16*)(scratch + OFF_XT_HI);
    __nv_bfloat16* xtLo   = (__nv_bfloat16*)(scratch + OFF_XT_LO);
    __nv_bfloat16* wqkvHi = (__nv_bfloat16*)(scratch + OFF_WQKV_HI);
    __nv_bfloat16* wqkvLo = (__nv_bfloat16*)(scratch + OFF_WQKV_LO);
    float* qkv_b          = scratch + OFF_QKV_B;
    __nv_bfloat16* wwgHi  = (__nv_bfloat16*)(scratch + OFF_WWG_HI);
    __nv_bfloat16* wwgLo  = (__nv_bfloat16*)(scratch + OFF_WWG_LO);
    __nv_bfloat16* c1wHi  = (__nv_bfloat16*)(scratch + OFF_C1WHI);
    __nv_bfloat16* c1wLo  = (__nv_bfloat16*)(scratch + OFF_C1WLO);
    __nv_bfloat16* c2wHi  = (__nv_bfloat16*)(scratch + OFF_C2WHI);
    __nv_bfloat16* c2wLo  = (__nv_bfloat16*)(scratch + OFF_C2WLO);
    __nv_bfloat16* qkvHi  = (__nv_bfloat16*)(scratch + OFF_QKVT_HI);
    __nv_bfloat16* qkvLo  = (__nv_bfloat16*)(scratch + OFF_QKVT_LO);
    float* Sg    = scratch + OFF_SG;
    float* Sl    = scratch + OFF_SL;
    __nv_bfloat16* gpHi   = (__nv_bfloat16*)(scratch + OFF_GP_HI);
    __nv_bfloat16* gpLo   = (__nv_bfloat16*)(scratch + OFF_GP_LO);
    __nv_bfloat16* gg2Hi  = (__nv_bfloat16*)(scratch + OFF_GG2_HI);
    __nv_bfloat16* gg2Lo  = (__nv_bfloat16*)(scratch + OFF_GG2_LO);
    float* gbar  = scratch + OFF_GBAR;
    float* gate  = scratch + OFF_GATE;
    __nv_bfloat16* goHi   = (__nv_bfloat16*)(scratch + OFF_GOUTT_HI);
    __nv_bfloat16* goLo   = (__nv_bfloat16*)(scratch + OFF_GOUTT_LO);
    float* gout2T = scratch + OFF_GOUT2T;
    float* h1    = scratch + OFF_H1;
    __nv_bfloat16* h1Hi   = (__nv_bfloat16*)(scratch + OFF_H1HI);
    __nv_bfloat16* h1Lo   = (__nv_bfloat16*)(scratch + OFF_H1LO);
    __nv_bfloat16* m1Hi   = (__nv_bfloat16*)(scratch + OFF_M1HI);
    __nv_bfloat16* m1Lo   = (__nv_bfloat16*)(scratch + OFF_M1LO);
    float* m2    = scratch + OFF_M2;

    constexpr int SMEM64  = 61440;   // BN=64: 2*(2*10240 + 2*5120)
    constexpr int SMEM128 = 81920;   // BN=128
    cudaFuncSetAttribute(gemm_mma<64, 1, 0>,  cudaFuncAttributeMaxDynamicSharedMemorySize, SMEM64);
    cudaFuncSetAttribute(gemm_mma<64, 0, 0>,  cudaFuncAttributeMaxDynamicSharedMemorySize, SMEM64);
    cudaFuncSetAttribute(gemm_mma<128, 1, 1>, cudaFuncAttributeMaxDynamicSharedMemorySize, SMEM128);

    // 0) weight splits (qkv stacked [theta; phi; g]) + bias concat + x transpose
    split_kernel<<<(C_ * C_ + 255) / 256, 256>>>(theta_w, wqkvHi, wqkvLo, C_ * C_);
    split_kernel<<<(C_ * C_ + 255) / 256, 256>>>(phi_w, wqkvHi + (size_t)C_ * C_, wqkvLo + (size_t)C_ * C_, C_ * C_);
    split_kernel<<<(C_ * C_ + 255) / 256, 256>>>(g_w, wqkvHi + (size_t)2 * C_ * C_, wqkvLo + (size_t)2 * C_ * C_, C_ * C_);
    split_kernel<<<(C_ * C_ + 255) / 256, 256>>>(wg_w, wwgHi, wwgLo, C_ * C_);
    split_kernel<<<(C4_ * C_ + 255) / 256, 256>>>(conv1_w, c1wHi, c1wLo, C4_ * C_);
    split_kernel<<<(C_ * C4_ + 255) / 256, 256>>>(conv2_w, c2wHi, c2wLo, C_ * C4_);
    concat_bias<<<6, 256>>>(theta_b, phi_b, g_b, qkv_b);
    {
        dim3 grid(L_ / 32, C_ / 32, B_);
        transpose_split_x<<<grid, dim3(32, 8)>>>(x, xtHi, xtLo);
    }

    // 1) fused qkv: qkvT[b,l,0:1536] = xT(b) @ [th;ph;g]^T + bias  (hi/lo out)
    {
        dim3 grid(C3_ / 64, L_ / 128, B_);
        gemm_mma<64, 1, 0><<<grid, 256, SMEM64>>>(
            xtHi, xtLo, wqkvHi, wqkvLo, qkv_b, nullptr, qkvHi, qkvLo,
            C_, C_, C_, C3_, (size_t)L_ * C_, 0, (size_t)L_ * C3_, 1.f);
    }

    // 2) Sg = scale*phT@thT^T ; Sl = scale*phT@ggT^T  (fp32)
    {
        dim3 grid(L_ / 64, L_ / 128, B_);
        gemm_mma<64, 0, 0><<<grid, 256, SMEM64>>>(
            qkvHi + C_, qkvLo + C_, qkvHi, qkvLo, nullptr, Sg, nullptr, nullptr,
            C_, C3_, C3_, L_, (size_t)L_ * C3_, (size_t)L_ * C3_, (size_t)L_ * L_, SCALE_);
        gemm_mma<64, 0, 0><<<grid, 256, SMEM64>>>(
            qkvHi + C_, qkvLo + C_, qkvHi + 2 * C_, qkvLo + 2 * C_, nullptr, Sl, nullptr, nullptr,
            C_, C3_, C3_, L_, (size_t)L_ * C3_, (size_t)L_ * C3_, (size_t)L_ * L_, SCALE_);
    }

    // 3) gbar ; softmax -> gp hi/lo ; local gate ; g transpose
    gbar_kernel<<<dim3(32, B_), 256>>>(qkvHi, qkvLo, gbar);
    softmax_split<<<B_ * L_, 256>>>(Sg, gpHi, gpLo);
    local_gate_kernel<<<dim3(L_ / 4, B_), 128>>>(Sl, gbar, wl_w, wl_b, gate);
    {
        dim3 grid(L_ / 32, C_ / 32, B_);
        transpose_g<<<grid, dim3(32, 8)>>>(qkvHi, qkvLo, gg2Hi, gg2Lo);
    }

    // 4) goutT[l,c] = gp @ gg2^T (hi/lo) ; gout2T = goutT @ wg^T + wg_b (fp32)
    {
        dim3 grid(C_ / 64, L_ / 128, B_);
        gemm_mma<64, 1, 0><<<grid, 256, SMEM64>>>(
            gpHi, gpLo, gg2Hi, gg2Lo, nullptr, nullptr, goHi, goLo,
            L_, L_, L_, C_, (size_t)L_ * L_, (size_t)CL_, (size_t)L_ * C_, 1.f);
        gemm_mma<64, 0, 0><<<grid, 256, SMEM64>>>(
            goHi, goLo, wwgHi, wwgLo, wg_b, gout2T, nullptr, nullptr,
            C_, C_, C_, C_, (size_t)L_ * C_, 0, (size_t)L_ * C_, 1.f);
    }

    // 5) LN1 -> h1 (fp32 + hi/lo)
    ln1_kernel<<<dim3(L_, B_), 256>>>(gout2T, gate, x, ln1_g, ln1_b, h1, h1Hi, h1Lo);

    // 6) MLP1: m1 = Mish(h1 @ conv1^T + b) -> hi/lo
    {
        dim3 grid(C4_ / 128, NR_ / 128, 1);
        gemm_mma<128, 1, 1><<<grid, 256, SMEM128>>>(
            h1Hi, h1Lo, c1wHi, c1wLo, conv1_b, nullptr, m1Hi, m1Lo,
            C_, C_, C_, C4_, 0, 0, 0, 1.f);
    }

    // 7) MLP2: m2 = m1 @ conv2^T + b -> fp32
    {
        dim3 grid(C_ / 64, NR_ / 128, 1);
        gemm_mma<64, 0, 0><<<grid, 256, SMEM64>>>(
            m1Hi, m1Lo, c2wHi, c2wLo, conv2_b, m2, nullptr, nullptr,
            C4_, C4_, C4_, C_, 0, 0, 0, 1.f);
    }

    // 8) LN2 + transpose out
    ln2_kernel<<<NR_, 256>>>(m2, h1, ln2_g, ln2_b, out);
}

// round 6
// speedup vs baseline: 2.1435x; 1.1010x over previous
#include <cuda_runtime.h>
#include <cuda_bf16.h>
#include <math.h>
#include <stdint.h>

// ============================================================================
// Problem constants
// ============================================================================
namespace {
constexpr int B_ = 8, C_ = 512, L_ = 256;
constexpr int CL_ = C_ * L_;           // 131072
constexpr int C3_ = 3 * C_;            // 1536
constexpr int C4_ = 4 * C_;            // 2048
constexpr int NR_ = L_ * B_;           // 2048
constexpr float SCALE_ = 0.044194173824159216f; // 512^-0.5

// ---------------- scratch offsets (float units) ----------------
constexpr size_t OFF_XT_HI   = 0;                                    // bf16 [B,L,C]
constexpr size_t OFF_XT_LO   = OFF_XT_HI   + (size_t)B_ * CL_ / 2;
constexpr size_t OFF_WQKV_HI = OFF_XT_LO   + (size_t)B_ * CL_ / 2;   // bf16 [3C,C]
constexpr size_t OFF_WQKV_LO = OFF_WQKV_HI + (size_t)C3_ * C_ / 2;
constexpr size_t OFF_QKV_B   = OFF_WQKV_LO + (size_t)C3_ * C_ / 2;   // f32 [1536]
constexpr size_t OFF_WWG_HI  = OFF_QKV_B   + 1536;
constexpr size_t OFF_WWG_LO  = OFF_WWG_HI  + (size_t)C_ * C_ / 2;
constexpr size_t OFF_C1WHI   = OFF_WWG_LO  + (size_t)C_ * C_ / 2;
constexpr size_t OFF_C1WLO   = OFF_C1WHI   + (size_t)C4_ * C_ / 2;
constexpr size_t OFF_C2WHI   = OFF_C1WLO   + (size_t)C4_ * C_ / 2;
constexpr size_t OFF_C2WLO   = OFF_C2WHI   + (size_t)C_ * C4_ / 2;
constexpr size_t OFF_QKVT_HI = OFF_C2WLO   + (size_t)C_ * C4_ / 2;   // bf16 [B,L,3C]
constexpr size_t OFF_QKVT_LO = OFF_QKVT_HI + (size_t)B_ * L_ * C3_ / 2;
constexpr size_t OFF_SG      = OFF_QKVT_LO + (size_t)B_ * L_ * C3_ / 2; // f32 [B,L,L]
constexpr size_t OFF_SL      = OFF_SG      + (size_t)B_ * L_ * L_;   // MUST follow SG
constexpr size_t OFF_GP_HI   = OFF_SL      + (size_t)B_ * L_ * L_;   // bf16 [B,L,L]
constexpr size_t OFF_GP_LO   = OFF_GP_HI   + (size_t)B_ * L_ * L_ / 2;
constexpr size_t OFF_GG2_HI  = OFF_GP_LO   + (size_t)B_ * L_ * L_ / 2; // bf16 [B,C,L]
constexpr size_t OFF_GG2_LO  = OFF_GG2_HI  + (size_t)B_ * CL_ / 2;
constexpr size_t OFF_GBAR    = OFF_GG2_LO  + (size_t)B_ * CL_ / 2;
constexpr size_t OFF_GATE    = OFF_GBAR    + (size_t)B_ * L_;
constexpr size_t OFF_GOUTT_HI= OFF_GATE    + (size_t)B_ * L_;        // bf16 [B,L,C]
constexpr size_t OFF_GOUTT_LO= OFF_GOUTT_HI+ (size_t)B_ * CL_ / 2;
constexpr size_t OFF_GOUT2T  = OFF_GOUTT_LO+ (size_t)B_ * CL_ / 2;   // f32 [B,L,C]
constexpr size_t OFF_H1      = OFF_GOUT2T  + (size_t)B_ * CL_;       // f32 [NR,C]
constexpr size_t OFF_H1HI    = OFF_H1      + (size_t)NR_ * C_;
constexpr size_t OFF_H1LO    = OFF_H1HI    + (size_t)NR_ * C_ / 2;
constexpr size_t OFF_M1HI    = OFF_H1LO    + (size_t)NR_ * C_ / 2;   // bf16 [NR,C4]
constexpr size_t OFF_M1LO    = OFF_M1HI    + (size_t)NR_ * C4_ / 2;
constexpr size_t OFF_M2      = OFF_M1LO    + (size_t)NR_ * C4_ / 2;  // f32 [NR,C]
constexpr size_t SCRATCH_TOTAL = OFF_M2    + (size_t)NR_ * C_;
} // namespace

__device__ __align__(256) float d_scratch[SCRATCH_TOTAL];

// ============================================================================
// PTX helpers — sm_80-era only (mma.sync / ldmatrix / cp.async).
// ============================================================================
__device__ __forceinline__ uint32_t smem_to_u32(const void* p) {
    uint32_t a;
    asm("{ .reg .u64 t; cvta.to.shared.u64 t, %1; cvt.u32.u64 %0, t; }" : "=r"(a) : "l"(p));
    return a;
}
__device__ __forceinline__ void ldmat4(uint32_t (&r)[4], uint32_t addr) {
    asm volatile("ldmatrix.sync.aligned.m8n8.x4.shared.b16 {%0,%1,%2,%3}, [%4];"
                 : "=r"(r[0]), "=r"(r[1]), "=r"(r[2]), "=r"(r[3]) : "r"(addr));
}
__device__ __forceinline__ void mma16816(float (&d)[4], const uint32_t (&a)[4], const uint32_t b0, const uint32_t b1) {
    asm volatile("mma.sync.aligned.m16n8k16.row.col.f32.bf16.bf16.f32 "
                 "{%0,%1,%2,%3}, {%4,%5,%6,%7}, {%8,%9}, {%0,%1,%2,%3};"
                 : "+f"(d[0]), "+f"(d[1]), "+f"(d[2]), "+f"(d[3])
                 : "r"(a[0]), "r"(a[1]), "r"(a[2]), "r"(a[3]), "r"(b0), "r"(b1));
}
__device__ __forceinline__ void cp16(uint32_t saddr, const void* g) {
    asm volatile("cp.async.cg.shared.global [%0], [%1], 16;" :: "r"(saddr), "l"(g));
}
#define CP_COMMIT() asm volatile("cp.async.commit_group;" ::: "memory")
template <int N>
__device__ __forceinline__ void cp_wait() {
    asm volatile("cp.async.wait_group %0;" :: "n"(N) : "memory");
}

namespace {

__device__ __forceinline__ float warpSum(float v) {
#pragma unroll
    for (int o = 16; o; o >>= 1) v += __shfl_xor_sync(0xffffffffu, v, o);
    return v;
}
__device__ __forceinline__ float warpMax(float v) {
#pragma unroll
    for (int o = 16; o; o >>= 1) v = fmaxf(v, __shfl_xor_sync(0xffffffffu, v, o));
    return v;
}
__device__ __forceinline__ float mishf(float v) {
    float sp = fmaxf(v, 0.f) + log1pf(__expf(-fabsf(v)));
    return v * tanhf(sp);
}

// ============================================================================
// bf16-split tensor-core GEMM, multistage cp.async pipeline.
// NT: A [M,K] K-contig (lda) hi/lo ; B [N,K] K-contig (ldb) hi/lo
// D = Ahi·Bhi^T + Ahi·Blo^T + Alo·Bhi^T (fp32 accum)
// v = scale*D (+ biasN); ACT=1 -> mish; OUTFMT 0: fp32; 1: bf16 hi/lo.
// FUSE=1: z encodes (sel = z>>3, b = z&7); B += sel*selB, out += sel*selO.
// ============================================================================
template <int BN, int OUTFMT, int ACT, int FUSE, int STAGES>
__global__ void __launch_bounds__(256) gemm_mma(
    const __nv_bfloat16* __restrict__ Ahi, const __nv_bfloat16* __restrict__ Alo,
    const __nv_bfloat16* __restrict__ Bhi, const __nv_bfloat16* __restrict__ Blo,
    const float* __restrict__ biasN,
    float* __restrict__ outF,
    __nv_bfloat16* __restrict__ outHi, __nv_bfloat16* __restrict__ outLo,
    int K, int lda, int ldb, int ldOut,
    size_t sA, size_t sB, size_t sO, size_t selB, size_t selO, float scale)
{
    constexpr int BM = 128, BK = 32;
    constexpr int SROW = 80;
    constexpr int ATILE = BM * SROW;         // 10240
    constexpr int BTILE = BN * SROW;
    constexpr int STAGE = 2 * ATILE + 2 * BTILE;
    constexpr int WN = BN / 4;
    constexpr int NFRAG = WN / 8;

    extern __shared__ char smem[];
    const uint32_t sb = smem_to_u32(smem);
    const int tid = threadIdx.x, lane = tid & 31, wid = tid >> 5;
    const int wm = wid & 1, wn = wid >> 1;
    const int m0 = blockIdx.y * BM, n0 = blockIdx.x * BN;
    const int z = blockIdx.z;
    const int b = FUSE ? (z & 7) : z;
    const int sel = FUSE ? (z >> 3) : 0;

    Ahi += (size_t)b * sA; Alo += (size_t)b * sA;
    Bhi += (size_t)b * sB + (size_t)sel * selB;
    Blo += (size_t)b * sB + (size_t)sel * selB;
    if (OUTFMT == 0) outF += (size_t)b * sO + (size_t)sel * selO;
    else { outHi += (size_t)b * sO + (size_t)sel * selO; outLo += (size_t)b * sO + (size_t)sel * selO; }

    float acc[4][NFRAG][4];
#pragma unroll
    for (int i = 0; i < 4; i++)
#pragma unroll
        for (int j = 0; j < NFRAG; j++)
#pragma unroll
            for (int q = 0; q < 4; q++) acc[i][j][q] = 0.f;

    auto load_stage = [&](int ch, int st) {
        const int k0 = ch * BK;
        const uint32_t base = sb + st * STAGE;
#pragma unroll
        for (int c = tid; c < BM * 4; c += 256) {
            int r = c >> 2, cc = c & 3;
            size_t go = (size_t)(m0 + r) * lda + k0 + cc * 8;
            uint32_t so = base + r * SROW + cc * 16;
            cp16(so, Ahi + go);
            cp16(so + ATILE, Alo + go);
        }
#pragma unroll
        for (int c = tid; c < BN * 4; c += 256) {
            int r = c >> 2, cc = c & 3;
            size_t go = (size_t)(n0 + r) * ldb + k0 + cc * 8;
            uint32_t so = base + 2 * ATILE + r * SROW + cc * 16;
            cp16(so, Bhi + go);
            cp16(so + BTILE, Blo + go);
        }
        CP_COMMIT();
    };

    const int nch = K / BK;
#pragma unroll
    for (int s = 0; s < STAGES - 1; s++) load_stage(s, s);

    int cs = 0;                                  // compute stage
    int ps = (STAGES - 1) % STAGES;              // prefetch stage
    for (int ch = 0; ch < nch; ch++) {
        cp_wait<STAGES - 2>();
        __syncthreads();
        const int pf = ch + STAGES - 1;
        if (pf < nch) load_stage(pf, ps);
        else CP_COMMIT();                        // empty group keeps accounting exact

        const uint32_t aBase = sb + cs * STAGE;
        const uint32_t bBase = aBase + 2 * ATILE;
#pragma unroll
        for (int ks = 0; ks < 2; ks++) {
            const uint32_t colOff = (uint32_t)(ks * 2 + (lane >> 4)) * 16;
            uint32_t a_hi[4][4], a_lo[4][4];
#pragma unroll
            for (int mi = 0; mi < 4; mi++) {
                uint32_t addr = aBase + (uint32_t)(wm * 64 + mi * 16 + (lane & 15)) * SROW + colOff;
                ldmat4(a_hi[mi], addr);
                ldmat4(a_lo[mi], addr + ATILE);
            }
#pragma unroll
            for (int nt = 0; nt < NFRAG / 2; nt++) {
                uint32_t addr = bBase + (uint32_t)(wn * WN + nt * 16 + (lane & 15)) * SROW + colOff;
                uint32_t bh[4], bl[4];
                ldmat4(bh, addr);
                ldmat4(bl, addr + BTILE);
#pragma unroll
                for (int half = 0; half < 2; half++) {
                    const int ni = nt * 2 + half;
#pragma unroll
                    for (int mi = 0; mi < 4; mi++) {
                        mma16816(acc[mi][ni], a_hi[mi], bh[half], bh[2 + half]);
                        mma16816(acc[mi][ni], a_hi[mi], bl[half], bl[2 + half]);
                        mma16816(acc[mi][ni], a_lo[mi], bh[half], bh[2 + half]);
                    }
                }
            }
        }
        cs = (cs + 1 == STAGES) ? 0 : cs + 1;
        ps = (ps + 1 == STAGES) ? 0 : ps + 1;
    }

    // ---------------- epilogue ----------------
    const int g = lane >> 2, tg = lane & 3;
#pragma unroll
    for (int mi = 0; mi < 4; mi++) {
#pragma unroll
        for (int ni = 0; ni < NFRAG; ni++) {
            const int col = n0 + wn * WN + ni * 8 + tg * 2;
            const float b0 = biasN ? biasN[col] : 0.f;
            const float b1 = biasN ? biasN[col + 1] : 0.f;
#pragma unroll
            for (int h = 0; h < 2; h++) {
                const int row = m0 + wm * 64 + mi * 16 + g + h * 8;
                float v0 = acc[mi][ni][h * 2 + 0] * scale + b0;
                float v1 = acc[mi][ni][h * 2 + 1] * scale + b1;
                if (ACT == 1) { v0 = mishf(v0); v1 = mishf(v1); }
                const size_t o = (size_t)row * ldOut + col;
                if (OUTFMT == 1) {
                    __nv_bfloat16 h0 = __float2bfloat16(v0);
                    __nv_bfloat16 h1 = __float2bfloat16(v1);
                    __nv_bfloat162 hp; hp.x = h0; hp.y = h1;
                    __nv_bfloat162 lp;
                    lp.x = __float2bfloat16(v0 - __bfloat162float(h0));
                    lp.y = __float2bfloat16(v1 - __bfloat162float(h1));
                    *(__nv_bfloat162*)(outHi + o) = hp;
                    *(__nv_bfloat162*)(outLo + o) = lp;
                } else {
                    float2 fp; fp.x = v0; fp.y = v1;
                    *(float2*)(outF + o) = fp;
                }
            }
        }
    }
}

// ============================================================================
// split_all: every weight matrix -> bf16 hi/lo, plus qkv bias concat. 1 launch.
// ============================================================================
__global__ void split_all(const float* __restrict__ tw, const float* __restrict__ pw,
                          const float* __restrict__ gw, const float* __restrict__ wgw,
                          const float* __restrict__ c1w, const float* __restrict__ c2w,
                          const float* __restrict__ tb, const float* __restrict__ pb,
                          const float* __restrict__ gb,
                          __nv_bfloat16* __restrict__ qkvHi, __nv_bfloat16* __restrict__ qkvLo,
                          __nv_bfloat16* __restrict__ wgHi, __nv_bfloat16* __restrict__ wgLo,
                          __nv_bfloat16* __restrict__ c1Hi, __nv_bfloat16* __restrict__ c1Lo,
                          __nv_bfloat16* __restrict__ c2Hi, __nv_bfloat16* __restrict__ c2Lo,
                          float* __restrict__ qkvb)
{
    constexpr int NW = C_ * C_;             // 262144
    constexpr int N1 = 3 * NW;              // qkv end
    constexpr int N2 = N1 + NW;             // wg end
    constexpr int N3 = N2 + C4_ * C_;       // conv1 end
    constexpr int N4 = N3 + C_ * C4_;       // conv2 end
    const int i = blockIdx.x * 256 + threadIdx.x;

    float v;
    __nv_bfloat16 *hi, *lo;
    int j;
    if (i < N1) {
        j = i & (NW - 1);
        const float* src = (i < NW) ? tw : (i < 2 * NW ? pw : gw);
        v = src[j]; hi = qkvHi + i; lo = qkvLo + i;
    } else if (i < N2) {
        j = i - N1; v = wgw[j]; hi = wgHi + j; lo = wgLo + j;
    } else if (i < N3) {
        j = i - N2; v = c1w[j]; hi = c1Hi + j; lo = c1Lo + j;
    } else if (i < N4) {
        j = i - N3; v = c2w[j]; hi = c2Hi + j; lo = c2Lo + j;
    } else if (i < N4 + C3_) {
        j = i - N4;
        qkvb[j] = (j < C_) ? tb[j] : (j < 2 * C_ ? pb[j - C_] : gb[j - 2 * C_]);
        return;
    } else return;
    __nv_bfloat16 h = __float2bfloat16(v);
    *hi = h;
    *lo = __float2bfloat16(v - __bfloat162float(h));
}

// ============================================================================
// transpose + split: x [B,C,L] f32 -> xT [B,L,C] bf16 hi/lo
// ============================================================================
__global__ void transpose_split_x(const float* __restrict__ x,
                                  __nv_bfloat16* __restrict__ hi,
                                  __nv_bfloat16* __restrict__ lo)
{
    __shared__ float t[32][33];
    const int b = blockIdx.z;
    const int l0 = blockIdx.x * 32, c0 = blockIdx.y * 32;
    const int tx = threadIdx.x, ty = threadIdx.y;
    const float* xb = x + (size_t)b * CL_;
#pragma unroll
    for (int j = 0; j < 4; j++)
        t[ty + j * 8][tx] = xb[(size_t)(c0 + ty + j * 8) * L_ + l0 + tx];
    __syncthreads();
#pragma unroll
    for (int j = 0; j < 4; j++) {
        int l = l0 + ty + j * 8;
        float v = t[tx][ty + j * 8];
        __nv_bfloat16 h = __float2bfloat16(v);
        size_t o = ((size_t)b * L_ + l) * C_ + c0 + tx;
        hi[o] = h;
        lo[o] = __float2bfloat16(v - __bfloat162float(h));
    }
}

// ============================================================================
// transpose bf16 pair: qkvT g-slice [B,L,3C @ 2C..3C] -> gg2 [B,C,L]
// ============================================================================
__global__ void transpose_g(const __nv_bfloat16* __restrict__ inHi,
                            const __nv_bfloat16* __restrict__ inLo,
                            __nv_bfloat16* __restrict__ outHi,
                            __nv_bfloat16* __restrict__ outLo)
{
    __shared__ __nv_bfloat16 th[32][34];
    __shared__ __nv_bfloat16 tl[32][34];
    const int b = blockIdx.z;
    const int l0 = blockIdx.x * 32, c0 = blockIdx.y * 32;
    const int tx = threadIdx.x, ty = threadIdx.y;
#pragma unroll
    for (int j = 0; j < 4; j++) {
        size_t idx = ((size_t)b * L_ + l0 + ty + j * 8) * C3_ + 2 * C_ + c0 + tx;
        th[ty + j * 8][tx] = inHi[idx];
        tl[ty + j * 8][tx] = inLo[idx];
    }
    __syncthreads();
#pragma unroll
    for (int j = 0; j < 4; j++) {
        int c = c0 + ty + j * 8;
        size_t o = ((size_t)b * C_ + c) * L_ + l0 + tx;
        outHi[o] = th[tx][ty + j * 8];
        outLo[o] = tl[tx][ty + j * 8];
    }
}

// ============================================================================
// gbar[b,m] = mean_c g[b,c,m] from qkvT g-slice. grid (32,B), 8 warps/block.
// ============================================================================
__global__ void gbar_kernel(const __nv_bfloat16* __restrict__ gHi,
                            const __nv_bfloat16* __restrict__ gLo,
                            float* __restrict__ gbar)
{
    const int b = blockIdx.y;
    const int m = blockIdx.x * 8 + (threadIdx.x >> 5);
    const int lane = threadIdx.x & 31;
    const size_t base = ((size_t)b * L_ + m) * C3_ + 2 * C_;
    float s = 0.f;
#pragma unroll
    for (int c = lane; c < C_; c += 32)
        s += __bfloat162float(gHi[base + c]) + __bfloat162float(gLo[base + c]);
    s = warpSum(s);
    if (lane == 0) gbar[b * L_ + m] = s * (1.f / C_);
}

// ============================================================================
// Fused: softmax(Sg row) -> gp hi/lo  AND  banded local gate from Sl row.
// grid (L, B), block 256.
// ============================================================================
__global__ void softmax_gate(const float* __restrict__ Sg,
                             const float* __restrict__ Sl,
                             const float* __restrict__ gbar,
                             const float* __restrict__ wlw,
                             const float* __restrict__ wlb,
                             __nv_bfloat16* __restrict__ pHi,
                             __nv_bfloat16* __restrict__ pLo,
                             float* __restrict__ gate)
{
    __shared__ float sm[16];
    const int l = blockIdx.x, b = blockIdx.y, tid = threadIdx.x;
    const int lane = tid & 31, w = tid >> 5;
    const size_t row = (size_t)b * L_ + l;

    // --- global softmax over Sg row ---
    float v = Sg[row * L_ + tid];
    float m = warpMax(v);
    if (lane == 0) sm[w] = m;
    __syncthreads();
    float M = -1e30f;
#pragma unroll
    for (int i = 0; i < 8; i++) M = fmaxf(M, sm[i]);
    float e = __expf(v - M);
    float s = warpSum(e);
    if (lane == 0) sm[8 + w] = s;
    __syncthreads();
    float T = 0.f;
#pragma unroll
    for (int i = 0; i < 8; i++) T += sm[8 + i];
    float p = e / T;
    __nv_bfloat16 h = __float2bfloat16(p);
    pHi[row * L_ + tid] = h;
    pLo[row * L_ + tid] = __float2bfloat16(p - __bfloat162float(h));

    // --- banded local gate (warp 0 only; zeros participate in softmax) ---
    if (w == 0) {
        const float* srow = Sl + row * L_;
        const float* gb = gbar + (size_t)b * L_;
        int m0 = l + lane - 32;
        int m1 = l + lane;
        bool v0 = (m0 >= 0) && (m0 < L_);
        bool v1 = (m1 >= 0) && (m1 < L_);
        float s0 = v0 ? srow[m0] : 0.f;
        float s1 = v1 ? srow[m1] : 0.f;
        float g0 = v0 ? gb[m0] : 0.f;
        float g1 = v1 ? gb[m1] : 0.f;
        float mx = warpMax(fmaxf(s0, s1));
        float e0 = __expf(s0 - mx), e1 = __expf(s1 - mx);
        float num = warpSum(e0 * g0 + e1 * g1);
        float den = warpSum(e0 + e1);
        if (lane == 0) {
            float pooled = num / den;
            float z = wlw[0] * pooled + wlb[0];
            gate[b * L_ + l] = 1.f / (1.f + __expf(-z));
        }
    }
}

// ============================================================================
// LN1: h = gout2T*gate + x ; h1 fp32 + bf16 hi/lo at row (l*B+b), [*,C]
// ============================================================================
__global__ void ln1_kernel(const float* __restrict__ gout2T,
                           const float* __restrict__ gate,
                           const float* __restrict__ x,
                           const float* __restrict__ g1, const float* __restrict__ b1,
                           float* __restrict__ h1,
                           __nv_bfloat16* __restrict__ h1hi,
                           __nv_bfloat16* __restrict__ h1lo)
{
    __shared__ float sm[16];
    int l = blockIdx.x, b = blockIdx.y, tid = threadIdx.x;
    int lane = tid & 31, w = tid >> 5;
    float gt = gate[b * L_ + l];
    size_t gbase = ((size_t)b * L_ + l) * C_;
    size_t xbase = (size_t)b * CL_ + l;
    float v0 = fmaf(gout2T[gbase + tid], gt, x[xbase + (size_t)tid * L_]);
    float v1 = fmaf(gout2T[gbase + tid + 256], gt, x[xbase + (size_t)(tid + 256) * L_]);
    float s = warpSum(v0 + v1);
    float q = warpSum(v0 * v0 + v1 * v1);
    if (lane == 0) { sm[w] = s; sm[8 + w] = q; }
    __syncthreads();
    float S = 0.f, Q = 0.f;
#pragma unroll
    for (int i = 0; i < 8; i++) { S += sm[i]; Q += sm[8 + i]; }
    float mean = S * (1.f / C_);
    float var = Q * (1.f / C_) - mean * mean;
    float r = rsqrtf(var + 1e-5f);
    size_t o = ((size_t)l * B_ + b) * C_;
    float y0 = (v0 - mean) * r * g1[tid] + b1[tid];
    float y1 = (v1 - mean) * r * g1[tid + 256] + b1[tid + 256];
    h1[o + tid] = y0;
    h1[o + tid + 256] = y1;
    __nv_bfloat16 h0b = __float2bfloat16(y0);
    __nv_bfloat16 h1b = __float2bfloat16(y1);
    h1hi[o + tid] = h0b;
    h1hi[o + tid + 256] = h1b;
    h1lo[o + tid] = __float2bfloat16(y0 - __bfloat162float(h0b));
    h1lo[o + tid + 256] = __float2bfloat16(y1 - __bfloat162float(h1b));
}

// ============================================================================
// LN2 + output transpose
// ============================================================================
__global__ void ln2_kernel(const float* __restrict__ m2,
                           const float* __restrict__ h1,
                           const float* __restrict__ g2, const float* __restrict__ b2,
                           float* __restrict__ out)
{
    __shared__ float sm[16];
    int row = blockIdx.x, tid = threadIdx.x;
    int lane = tid & 31, w = tid >> 5;
    int l = row / B_, b = row % B_;
    size_t base = (size_t)row * C_;
    float v0 = m2[base + tid] + h1[base + tid];
    float v1 = m2[base + tid + 256] + h1[base + tid + 256];
    float s = warpSum(v0 + v1);
    float q = warpSum(v0 * v0 + v1 * v1);
    if (lane == 0) { sm[w] = s; sm[8 + w] = q; }
    __syncthreads();
    float S = 0.f, Q = 0.f;
#pragma unroll
    for (int i = 0; i < 8; i++) { S += sm[i]; Q += sm[8 + i]; }
    float mean = S * (1.f / C_);
    float var = Q * (1.f / C_) - mean * mean;
    float r = rsqrtf(var + 1e-5f);
    size_t ob = (size_t)b * CL_ + l;
    out[ob + (size_t)tid * L_]         = (v0 - mean) * r * g2[tid] + b2[tid];
    out[ob + (size_t)(tid + 256) * L_] = (v1 - mean) * r * g2[tid + 256] + b2[tid + 256];
}

} // namespace

// ============================================================================
// Host launcher
// ============================================================================
extern "C" void kernel_launch(void* const* d_in, const int* in_sizes, int n_in,
                              void* d_out, int out_size)
{
    (void)in_sizes; (void)n_in; (void)out_size;
    float* scratch = nullptr;
    cudaGetSymbolAddress((void**)&scratch, d_scratch);

    const float* x       = (const float*)d_in[0];
    const float* theta_w = (const float*)d_in[1];
    const float* theta_b = (const float*)d_in[2];
    const float* phi_w   = (const float*)d_in[3];
    const float* phi_b   = (const float*)d_in[4];
    const float* g_w     = (const float*)d_in[5];
    const float* g_b     = (const float*)d_in[6];
    const float* wl_w    = (const float*)d_in[7];
    const float* wl_b    = (const float*)d_in[8];
    const float* wg_w    = (const float*)d_in[9];
    const float* wg_b    = (const float*)d_in[10];
    const float* conv1_w = (const float*)d_in[11];
    const float* conv1_b = (const float*)d_in[12];
    const float* conv2_w = (const float*)d_in[13];
    const float* conv2_b = (const float*)d_in[14];
    const float* ln1_g   = (const float*)d_in[15];
    const float* ln1_b   = (const float*)d_in[16];
    const float* ln2_g   = (const float*)d_in[17];
    const float* ln2_b   = (const float*)d_in[18];
    float* out = (float*)d_out;

    __nv_bfloat16* xtHi   = (__nv_bfloat16*)(scratch + OFF_XT_HI);
    __nv_bfloat16* xtLo   = (__nv_bfloat16*)(scratch + OFF_XT_LO);
    __nv_bfloat16* wqkvHi = (__nv_bfloat16*)(scratch + OFF_WQKV_HI);
    __nv_bfloat16* wqkvLo = (__nv_bfloat16*)(scratch + OFF_WQKV_LO);
    float* qkv_b          = scratch + OFF_QKV_B;
    __nv_bfloat16* wwgHi  = (__nv_bfloat16*)(scratch + OFF_WWG_HI);
    __nv_bfloat16* wwgLo  = (__nv_bfloat16*)(scratch + OFF_WWG_LO);
    __nv_bfloat16* c1wHi  = (__nv_bfloat16*)(scratch + OFF_C1WHI);
    __nv_bfloat16* c1wLo  = (__nv_bfloat16*)(scratch + OFF_C1WLO);
    __nv_bfloat16* c2wHi  = (__nv_bfloat16*)(scratch + OFF_C2WHI);
    __nv_bfloat16* c2wLo  = (__nv_bfloat16*)(scratch + OFF_C2WLO);
    __nv_bfloat16* qkvHi  = (__nv_bfloat16*)(scratch + OFF_QKVT_HI);
    __nv_bfloat16* qkvLo  = (__nv_bfloat16*)(scratch + OFF_QKVT_LO);
    float* Sg    = scratch + OFF_SG;
    __nv_bfloat16* gpHi   = (__nv_bfloat16*)(scratch + OFF_GP_HI);
    __nv_bfloat16* gpLo   = (__nv_bfloat16*)(scratch + OFF_GP_LO);
    __nv_bfloat16* gg2Hi  = (__nv_bfloat16*)(scratch + OFF_GG2_HI);
    __nv_bfloat16* gg2Lo  = (__nv_bfloat16*)(scratch + OFF_GG2_LO);
    float* gbar  = scratch + OFF_GBAR;
    float* gate  = scratch + OFF_GATE;
    __nv_bfloat16* goHi   = (__nv_bfloat16*)(scratch + OFF_GOUTT_HI);
    __nv_bfloat16* goLo   = (__nv_bfloat16*)(scratch + OFF_GOUTT_LO);
    float* gout2T = scratch + OFF_GOUT2T;
    float* h1    = scratch + OFF_H1;
    __nv_bfloat16* h1Hi   = (__nv_bfloat16*)(scratch + OFF_H1HI);
    __nv_bfloat16* h1Lo   = (__nv_bfloat16*)(scratch + OFF_H1LO);
    __nv_bfloat16* m1Hi   = (__nv_bfloat16*)(scratch + OFF_M1HI);
    __nv_bfloat16* m1Lo   = (__nv_bfloat16*)(scratch + OFF_M1LO);
    float* m2    = scratch + OFF_M2;

    constexpr int SMEM64_3  = 92160;   // BN=64, 3 stages: 3*30720
    constexpr int SMEM128_2 = 81920;   // BN=128, 2 stages: 2*40960
    cudaFuncSetAttribute(gemm_mma<64, 0, 0, 1, 3>,  cudaFuncAttributeMaxDynamicSharedMemorySize, SMEM64_3);
    cudaFuncSetAttribute(gemm_mma<64, 1, 0, 0, 3>,  cudaFuncAttributeMaxDynamicSharedMemorySize, SMEM64_3);
    cudaFuncSetAttribute(gemm_mma<64, 0, 0, 0, 3>,  cudaFuncAttributeMaxDynamicSharedMemorySize, SMEM64_3);
    cudaFuncSetAttribute(gemm_mma<128, 1, 0, 0, 2>, cudaFuncAttributeMaxDynamicSharedMemorySize, SMEM128_2);
    cudaFuncSetAttribute(gemm_mma<128, 1, 1, 0, 2>, cudaFuncAttributeMaxDynamicSharedMemorySize, SMEM128_2);

    // 0) all weight splits + bias concat (1 launch) ; x transpose/split
    {
        constexpr int TOTAL = 3 * C_ * C_ + C_ * C_ + C4_ * C_ + C_ * C4_ + C3_;
        split_all<<<(TOTAL + 255) / 256, 256>>>(
            theta_w, phi_w, g_w, wg_w, conv1_w, conv2_w, theta_b, phi_b, g_b,
            wqkvHi, wqkvLo, wwgHi, wwgLo, c1wHi, c1wLo, c2wHi, c2wLo, qkv_b);
        dim3 grid(L_ / 32, C_ / 32, B_);
        transpose_split_x<<<grid, dim3(32, 8)>>>(x, xtHi, xtLo);
    }

    // 1) fused qkv (BN=128): qkvT[b,l,:] = xT(b) @ [th;ph;g]^T + bias
    {
        dim3 grid(C3_ / 128, L_ / 128, B_);
        gemm_mma<128, 1, 0, 0, 2><<<grid, 256, SMEM128_2>>>(
            xtHi, xtLo, wqkvHi, wqkvLo, qkv_b, nullptr, qkvHi, qkvLo,
            C_, C_, C_, C3_, (size_t)L_ * C_, 0, (size_t)L_ * C3_, 0, 0, 1.f);
    }

    // 2) gbar (needs only qkv) ; g transpose
    gbar_kernel<<<dim3(32, B_), 256>>>(qkvHi, qkvLo, gbar);
    {
        dim3 grid(L_ / 32, C_ / 32, B_);
        transpose_g<<<grid, dim3(32, 8)>>>(qkvHi, qkvLo, gg2Hi, gg2Lo);
    }

    // 3) Sg & Sl in ONE launch (sel = z>>3: 0 -> theta/Sg, 1 -> g/Sl)
    {
        dim3 grid(L_ / 64, L_ / 128, 2 * B_);
        gemm_mma<64, 0, 0, 1, 3><<<grid, 256, SMEM64_3>>>(
            qkvHi + C_, qkvLo + C_, qkvHi, qkvLo, nullptr, Sg, nullptr, nullptr,
            C_, C3_, C3_, L_, (size_t)L_ * C3_, (size_t)L_ * C3_, (size_t)L_ * L_,
            (size_t)(2 * C_), (size_t)B_ * L_ * L_, SCALE_);
    }

    // 4) fused softmax + local gate
    softmax_gate<<<dim3(L_, B_), 256>>>(Sg, Sg + (size_t)B_ * L_ * L_, gbar,
                                        wl_w, wl_b, gpHi, gpLo, gate);

    // 5) goutT = gp @ gg2^T (hi/lo) ; gout2T = goutT @ wg^T + wg_b (fp32)
    {
        dim3 grid(C_ / 64, L_ / 128, B_);
        gemm_mma<64, 1, 0, 0, 3><<<grid, 256, SMEM64_3>>>(
            gpHi, gpLo, gg2Hi, gg2Lo, nullptr, nullptr, goHi, goLo,
            L_, L_, L_, C_, (size_t)L_ * L_, (size_t)CL_, (size_t)L_ * C_, 0, 0, 1.f);
        gemm_mma<64, 0, 0, 0, 3><<<grid, 256, SMEM64_3>>>(
            goHi, goLo, wwgHi, wwgLo, wg_b, gout2T, nullptr, nullptr,
            C_, C_, C_, C_, (size_t)L_ * C_, 0, (size_t)L_ * C_, 0, 0, 1.f);
    }

    // 6) LN1 -> h1 (fp32 + hi/lo)
    ln1_kernel<<<dim3(L_, B_), 256>>>(gout2T, gate, x, ln1_g, ln1_b, h1, h1Hi, h1Lo);

    // 7) MLP1: m1 = Mish(h1 @ conv1^T + b) -> hi/lo
    {
        dim3 grid(C4_ / 128, NR_ / 128, 1);
        gemm_mma<128, 1, 1, 0, 2><<<grid, 256, SMEM128_2>>>(
            h1Hi, h1Lo, c1wHi, c1wLo, conv1_b, nullptr, m1Hi, m1Lo,
            C_, C_, C_, C4_, 0, 0, 0, 0, 0, 1.f);
    }

    // 8) MLP2: m2 = m1 @ conv2^T + b -> fp32
    {
        dim3 grid(C_ / 64, NR_ / 128, 1);
        gemm_mma<64, 0, 0, 0, 3><<<grid, 256, SMEM64_3>>>(
            m1Hi, m1Lo, c2wHi, c2wLo, conv2_b, m2, nullptr, nullptr,
            C4_, C4_, C4_, C_, 0, 0, 0, 0, 0, 1.f);
    }

    // 9) LN2 + transpose out
    ln2_kernel<<<NR_, 256>>>(m2, h1, ln2_g, ln2_b, out);
}

// round 7
// speedup vs baseline: 2.2769x; 1.0623x over previous
#include <cuda_runtime.h>
#include <cuda_bf16.h>
#include <math.h>
#include <stdint.h>

// ============================================================================
// Problem constants
// ============================================================================
namespace {
constexpr int B_ = 8, C_ = 512, L_ = 256;
constexpr int CL_ = C_ * L_;           // 131072
constexpr int C3_ = 3 * C_;            // 1536
constexpr int C4_ = 4 * C_;            // 2048
constexpr int NR_ = L_ * B_;           // 2048
constexpr float SCALE_ = 0.044194173824159216f; // 512^-0.5

// ---------------- scratch offsets (float units) ----------------
constexpr size_t OFF_XT_HI   = 0;                                    // bf16 [B,L,C]
constexpr size_t OFF_XT_LO   = OFF_XT_HI   + (size_t)B_ * CL_ / 2;
constexpr size_t OFF_WQKV_HI = OFF_XT_LO   + (size_t)B_ * CL_ / 2;   // bf16 [3C,C]
constexpr size_t OFF_WQKV_LO = OFF_WQKV_HI + (size_t)C3_ * C_ / 2;
constexpr size_t OFF_QKV_B   = OFF_WQKV_LO + (size_t)C3_ * C_ / 2;   // f32 [1536]
constexpr size_t OFF_WWG_HI  = OFF_QKV_B   + 1536;
constexpr size_t OFF_WWG_LO  = OFF_WWG_HI  + (size_t)C_ * C_ / 2;
constexpr size_t OFF_C1WHI   = OFF_WWG_LO  + (size_t)C_ * C_ / 2;
constexpr size_t OFF_C1WLO   = OFF_C1WHI   + (size_t)C4_ * C_ / 2;
constexpr size_t OFF_C2WHI   = OFF_C1WLO   + (size_t)C4_ * C_ / 2;
constexpr size_t OFF_C2WLO   = OFF_C2WHI   + (size_t)C_ * C4_ / 2;
constexpr size_t OFF_QKVT_HI = OFF_C2WLO   + (size_t)C_ * C4_ / 2;   // bf16 [B,L,3C]
constexpr size_t OFF_QKVT_LO = OFF_QKVT_HI + (size_t)B_ * L_ * C3_ / 2;
constexpr size_t OFF_SG      = OFF_QKVT_LO + (size_t)B_ * L_ * C3_ / 2; // f32 [B,L,L]
constexpr size_t OFF_SL      = OFF_SG      + (size_t)B_ * L_ * L_;   // MUST follow SG
constexpr size_t OFF_GP_HI   = OFF_SL      + (size_t)B_ * L_ * L_;   // bf16 [B,L,L]
constexpr size_t OFF_GP_LO   = OFF_GP_HI   + (size_t)B_ * L_ * L_ / 2;
constexpr size_t OFF_GG2_HI  = OFF_GP_LO   + (size_t)B_ * L_ * L_ / 2; // bf16 [B,C,L]
constexpr size_t OFF_GG2_LO  = OFF_GG2_HI  + (size_t)B_ * CL_ / 2;
constexpr size_t OFF_GBAR    = OFF_GG2_LO  + (size_t)B_ * CL_ / 2;
constexpr size_t OFF_GATE    = OFF_GBAR    + (size_t)B_ * L_;
constexpr size_t OFF_GOUTT_HI= OFF_GATE    + (size_t)B_ * L_;        // bf16 [B,L,C]
constexpr size_t OFF_GOUTT_LO= OFF_GOUTT_HI+ (size_t)B_ * CL_ / 2;
constexpr size_t OFF_GOUT2T  = OFF_GOUTT_LO+ (size_t)B_ * CL_ / 2;   // f32 [B,L,C]
constexpr size_t OFF_H1      = OFF_GOUT2T  + (size_t)B_ * CL_;       // f32 [NR,C]
constexpr size_t OFF_H1HI    = OFF_H1      + (size_t)NR_ * C_;
constexpr size_t OFF_H1LO    = OFF_H1HI    + (size_t)NR_ * C_ / 2;
constexpr size_t OFF_M1HI    = OFF_H1LO    + (size_t)NR_ * C_ / 2;   // bf16 [NR,C4]
constexpr size_t OFF_M1LO    = OFF_M1HI    + (size_t)NR_ * C4_ / 2;
constexpr size_t OFF_M2      = OFF_M1LO    + (size_t)NR_ * C4_ / 2;  // f32 [NR,C]
constexpr size_t SCRATCH_TOTAL = OFF_M2    + (size_t)NR_ * C_;
} // namespace

__device__ __align__(256) float d_scratch[SCRATCH_TOTAL];

// ============================================================================
// PTX helpers — sm_80-era only (mma.sync / ldmatrix / cp.async).
// ============================================================================
__device__ __forceinline__ uint32_t smem_to_u32(const void* p) {
    uint32_t a;
    asm("{ .reg .u64 t; cvta.to.shared.u64 t, %1; cvt.u32.u64 %0, t; }" : "=r"(a) : "l"(p));
    return a;
}
__device__ __forceinline__ void ldmat4(uint32_t (&r)[4], uint32_t addr) {
    asm volatile("ldmatrix.sync.aligned.m8n8.x4.shared.b16 {%0,%1,%2,%3}, [%4];"
                 : "=r"(r[0]), "=r"(r[1]), "=r"(r[2]), "=r"(r[3]) : "r"(addr));
}
__device__ __forceinline__ void mma16816(float (&d)[4], const uint32_t (&a)[4], const uint32_t b0, const uint32_t b1) {
    asm volatile("mma.sync.aligned.m16n8k16.row.col.f32.bf16.bf16.f32 "
                 "{%0,%1,%2,%3}, {%4,%5,%6,%7}, {%8,%9}, {%0,%1,%2,%3};"
                 : "+f"(d[0]), "+f"(d[1]), "+f"(d[2]), "+f"(d[3])
                 : "r"(a[0]), "r"(a[1]), "r"(a[2]), "r"(a[3]), "r"(b0), "r"(b1));
}
__device__ __forceinline__ void cp16(uint32_t saddr, const void* g) {
    asm volatile("cp.async.cg.shared.global [%0], [%1], 16;" :: "r"(saddr), "l"(g));
}
#define CP_COMMIT() asm volatile("cp.async.commit_group;" ::: "memory")
template <int N>
__device__ __forceinline__ void cp_wait() {
    asm volatile("cp.async.wait_group %0;" :: "n"(N) : "memory");
}

namespace {

__device__ __forceinline__ float warpSum(float v) {
#pragma unroll
    for (int o = 16; o; o >>= 1) v += __shfl_xor_sync(0xffffffffu, v, o);
    return v;
}
__device__ __forceinline__ float warpMax(float v) {
#pragma unroll
    for (int o = 16; o; o >>= 1) v = fmaxf(v, __shfl_xor_sync(0xffffffffu, v, o));
    return v;
}
__device__ __forceinline__ float mishf(float v) {
    float sp = fmaxf(v, 0.f) + log1pf(__expf(-fabsf(v)));
    return v * tanhf(sp);
}

// ============================================================================
// bf16-split tensor-core GEMM, multistage cp.async pipeline, templated BK.
// NT: A [M,K] K-contig (lda) hi/lo ; B [N,K] K-contig (ldb) hi/lo
// D = Ahi·Bhi^T + Ahi·Blo^T + Alo·Bhi^T (fp32 accum)
// v = scale*D (+ biasN); ACT=1 -> mish; OUTFMT 0: fp32; 1: bf16 hi/lo.
// FUSE=1: z encodes (sel = z>>3, b = z&7); B += sel*selB, out += sel*selO.
// ============================================================================
template <int BN, int OUTFMT, int ACT, int FUSE, int STAGES, int KB>
__global__ void __launch_bounds__(256) gemm_mma(
    const __nv_bfloat16* __restrict__ Ahi, const __nv_bfloat16* __restrict__ Alo,
    const __nv_bfloat16* __restrict__ Bhi, const __nv_bfloat16* __restrict__ Blo,
    const float* __restrict__ biasN,
    float* __restrict__ outF,
    __nv_bfloat16* __restrict__ outHi, __nv_bfloat16* __restrict__ outLo,
    int K, int lda, int ldb, int ldOut,
    size_t sA, size_t sB, size_t sO, size_t selB, size_t selO, float scale)
{
    constexpr int BM = 128;
    constexpr int SROW = KB * 2 + 16;        // bytes/row: data + 16B pad
    constexpr int CHR = KB / 8;              // 16B chunks per row
    constexpr int ATILE = BM * SROW;
    constexpr int BTILE = BN * SROW;
    constexpr int STAGE = 2 * ATILE + 2 * BTILE;
    constexpr int WN = BN / 4;
    constexpr int NFRAG = WN / 8;
    constexpr int NKS = KB / 16;             // k16 steps per chunk

    extern __shared__ char smem[];
    const uint32_t sb = smem_to_u32(smem);
    const int tid = threadIdx.x, lane = tid & 31, wid = tid >> 5;
    const int wm = wid & 1, wn = wid >> 1;
    const int m0 = blockIdx.y * BM, n0 = blockIdx.x * BN;
    const int z = blockIdx.z;
    const int b = FUSE ? (z & 7) : z;
    const int sel = FUSE ? (z >> 3) : 0;

    Ahi += (size_t)b * sA; Alo += (size_t)b * sA;
    Bhi += (size_t)b * sB + (size_t)sel * selB;
    Blo += (size_t)b * sB + (size_t)sel * selB;
    if (OUTFMT == 0) outF += (size_t)b * sO + (size_t)sel * selO;
    else { outHi += (size_t)b * sO + (size_t)sel * selO; outLo += (size_t)b * sO + (size_t)sel * selO; }

    float acc[4][NFRAG][4];
#pragma unroll
    for (int i = 0; i < 4; i++)
#pragma unroll
        for (int j = 0; j < NFRAG; j++)
#pragma unroll
            for (int q = 0; q < 4; q++) acc[i][j][q] = 0.f;

    auto load_stage = [&](int ch, int st) {
        const int k0 = ch * KB;
        const uint32_t base = sb + st * STAGE;
#pragma unroll
        for (int c = tid; c < BM * CHR; c += 256) {
            int r = c / CHR, cc = c % CHR;
            size_t go = (size_t)(m0 + r) * lda + k0 + cc * 8;
            uint32_t so = base + r * SROW + cc * 16;
            cp16(so, Ahi + go);
            cp16(so + ATILE, Alo + go);
        }
#pragma unroll
        for (int c = tid; c < BN * CHR; c += 256) {
            int r = c / CHR, cc = c % CHR;
            size_t go = (size_t)(n0 + r) * ldb + k0 + cc * 8;
            uint32_t so = base + 2 * ATILE + r * SROW + cc * 16;
            cp16(so, Bhi + go);
            cp16(so + BTILE, Blo + go);
        }
        CP_COMMIT();
    };

    const int nch = K / KB;
#pragma unroll
    for (int s = 0; s < STAGES - 1; s++) load_stage(s, s);

    int cs = 0;                                  // compute stage
    int ps = (STAGES - 1) % STAGES;              // prefetch stage
    for (int ch = 0; ch < nch; ch++) {
        cp_wait<STAGES - 2>();
        __syncthreads();
        const int pf = ch + STAGES - 1;
        if (pf < nch) load_stage(pf, ps);
        else CP_COMMIT();                        // empty group keeps accounting exact

        const uint32_t aBase = sb + cs * STAGE;
        const uint32_t bBase = aBase + 2 * ATILE;
#pragma unroll
        for (int ks = 0; ks < NKS; ks++) {
            const uint32_t colOff = (uint32_t)(ks * 2 + (lane >> 4)) * 16;
            uint32_t a_hi[4][4], a_lo[4][4];
#pragma unroll
            for (int mi = 0; mi < 4; mi++) {
                uint32_t addr = aBase + (uint32_t)(wm * 64 + mi * 16 + (lane & 15)) * SROW + colOff;
                ldmat4(a_hi[mi], addr);
                ldmat4(a_lo[mi], addr + ATILE);
            }
#pragma unroll
            for (int nt = 0; nt < NFRAG / 2; nt++) {
                uint32_t addr = bBase + (uint32_t)(wn * WN + nt * 16 + (lane & 15)) * SROW + colOff;
                uint32_t bh[4], bl[4];
                ldmat4(bh, addr);
                ldmat4(bl, addr + BTILE);
#pragma unroll
                for (int half = 0; half < 2; half++) {
                    const int ni = nt * 2 + half;
#pragma unroll
                    for (int mi = 0; mi < 4; mi++) {
                        mma16816(acc[mi][ni], a_hi[mi], bh[half], bh[2 + half]);
                        mma16816(acc[mi][ni], a_hi[mi], bl[half], bl[2 + half]);
                        mma16816(acc[mi][ni], a_lo[mi], bh[half], bh[2 + half]);
                    }
                }
            }
        }
        cs = (cs + 1 == STAGES) ? 0 : cs + 1;
        ps = (ps + 1 == STAGES) ? 0 : ps + 1;
    }

    // ---------------- epilogue ----------------
    const int g = lane >> 2, tg = lane & 3;
#pragma unroll
    for (int mi = 0; mi < 4; mi++) {
#pragma unroll
        for (int ni = 0; ni < NFRAG; ni++) {
            const int col = n0 + wn * WN + ni * 8 + tg * 2;
            const float b0 = biasN ? biasN[col] : 0.f;
            const float b1 = biasN ? biasN[col + 1] : 0.f;
#pragma unroll
            for (int h = 0; h < 2; h++) {
                const int row = m0 + wm * 64 + mi * 16 + g + h * 8;
                float v0 = acc[mi][ni][h * 2 + 0] * scale + b0;
                float v1 = acc[mi][ni][h * 2 + 1] * scale + b1;
                if (ACT == 1) { v0 = mishf(v0); v1 = mishf(v1); }
                const size_t o = (size_t)row * ldOut + col;
                if (OUTFMT == 1) {
                    __nv_bfloat16 h0 = __float2bfloat16(v0);
                    __nv_bfloat16 h1 = __float2bfloat16(v1);
                    __nv_bfloat162 hp; hp.x = h0; hp.y = h1;
                    __nv_bfloat162 lp;
                    lp.x = __float2bfloat16(v0 - __bfloat162float(h0));
                    lp.y = __float2bfloat16(v1 - __bfloat162float(h1));
                    *(__nv_bfloat162*)(outHi + o) = hp;
                    *(__nv_bfloat162*)(outLo + o) = lp;
                } else {
                    float2 fp; fp.x = v0; fp.y = v1;
                    *(float2*)(outF + o) = fp;
                }
            }
        }
    }
}

// ============================================================================
// prep_all: ONE launch = all weight splits + qkv bias concat + x transpose.
// Blocks [0, NSPLIT) do splits; blocks [NSPLIT, NSPLIT+1024) transpose x.
// ============================================================================
constexpr int PREP_SPLIT_TOTAL = 3 * C_ * C_ + C_ * C_ + C4_ * C_ + C_ * C4_ + C3_;
constexpr int PREP_NSPLIT = (PREP_SPLIT_TOTAL + 255) / 256;   // 12294
constexpr int PREP_NT = (L_ / 32) * (C_ / 32) * B_;           // 1024

__global__ void prep_all(const float* __restrict__ x,
                         const float* __restrict__ tw, const float* __restrict__ pw,
                         const float* __restrict__ gw, const float* __restrict__ wgw,
                         const float* __restrict__ c1w, const float* __restrict__ c2w,
                         const float* __restrict__ tb, const float* __restrict__ pb,
                         const float* __restrict__ gb,
                         __nv_bfloat16* __restrict__ qkvHi, __nv_bfloat16* __restrict__ qkvLo,
                         __nv_bfloat16* __restrict__ wgHi, __nv_bfloat16* __restrict__ wgLo,
                         __nv_bfloat16* __restrict__ c1Hi, __nv_bfloat16* __restrict__ c1Lo,
                         __nv_bfloat16* __restrict__ c2Hi, __nv_bfloat16* __restrict__ c2Lo,
                         float* __restrict__ qkvb,
                         __nv_bfloat16* __restrict__ xtHi, __nv_bfloat16* __restrict__ xtLo)
{
    __shared__ float t[32][33];
    const int bid = blockIdx.x;
    if (bid < PREP_NSPLIT) {
        constexpr int NW = C_ * C_;
        constexpr int N1 = 3 * NW;
        constexpr int N2 = N1 + NW;
        constexpr int N3 = N2 + C4_ * C_;
        constexpr int N4 = N3 + C_ * C4_;
        const int i = bid * 256 + threadIdx.x;
        float v;
        __nv_bfloat16 *hi, *lo;
        int j;
        if (i < N1) {
            j = i & (NW - 1);
            const float* src = (i < NW) ? tw : (i < 2 * NW ? pw : gw);
            v = src[j]; hi = qkvHi + i; lo = qkvLo + i;
        } else if (i < N2) {
            j = i - N1; v = wgw[j]; hi = wgHi + j; lo = wgLo + j;
        } else if (i < N3) {
            j = i - N2; v = c1w[j]; hi = c1Hi + j; lo = c1Lo + j;
        } else if (i < N4) {
            j = i - N3; v = c2w[j]; hi = c2Hi + j; lo = c2Lo + j;
        } else if (i < N4 + C3_) {
            j = i - N4;
            qkvb[j] = (j < C_) ? tb[j] : (j < 2 * C_ ? pb[j - C_] : gb[j - 2 * C_]);
            return;
        } else return;
        __nv_bfloat16 h = __float2bfloat16(v);
        *hi = h;
        *lo = __float2bfloat16(v - __bfloat162float(h));
    } else {
        // transpose+split x: decode (l0, c0, b)
        const int tI = bid - PREP_NSPLIT;
        const int b = tI >> 7;
        const int rem = tI & 127;
        const int c0 = (rem & 15) * 32;
        const int l0 = (rem >> 4) * 32;
        const int tx = threadIdx.x & 31, ty = threadIdx.x >> 5;
        const float* xb = x + (size_t)b * CL_;
#pragma unroll
        for (int j = 0; j < 4; j++)
            t[ty + j * 8][tx] = xb[(size_t)(c0 + ty + j * 8) * L_ + l0 + tx];
        __syncthreads();
#pragma unroll
        for (int j = 0; j < 4; j++) {
            int l = l0 + ty + j * 8;
            float v = t[tx][ty + j * 8];
            __nv_bfloat16 h = __float2bfloat16(v);
            size_t o = ((size_t)b * L_ + l) * C_ + c0 + tx;
            xtHi[o] = h;
            xtLo[o] = __float2bfloat16(v - __bfloat162float(h));
        }
    }
}

// ============================================================================
// transpose_g + gbar in ONE kernel. grid (L/32, B), 256 threads.
// Each block handles a 32-l slab: transposes all 16 c-tiles of the g slice,
// then computes gbar for its 32 l values (coalesced c-contiguous reads).
// ============================================================================
__global__ void gtrans_gbar(const __nv_bfloat16* __restrict__ inHi,
                            const __nv_bfloat16* __restrict__ inLo,
                            __nv_bfloat16* __restrict__ outHi,
                            __nv_bfloat16* __restrict__ outLo,
                            float* __restrict__ gbar)
{
    __shared__ __nv_bfloat16 th[32][34];
    __shared__ __nv_bfloat16 tl[32][34];
    const int b = blockIdx.y;
    const int l0 = blockIdx.x * 32;
    const int tx = threadIdx.x & 31, ty = threadIdx.x >> 5;

    for (int ct = 0; ct < 16; ct++) {
        const int c0 = ct * 32;
#pragma unroll
        for (int j = 0; j < 4; j++) {
            size_t idx = ((size_t)b * L_ + l0 + ty + j * 8) * C3_ + 2 * C_ + c0 + tx;
            th[ty + j * 8][tx] = inHi[idx];
            tl[ty + j * 8][tx] = inLo[idx];
        }
        __syncthreads();
#pragma unroll
        for (int j = 0; j < 4; j++) {
            int c = c0 + ty + j * 8;
            size_t o = ((size_t)b * C_ + c) * L_ + l0 + tx;
            outHi[o] = th[tx][ty + j * 8];
            outLo[o] = tl[tx][ty + j * 8];
        }
        __syncthreads();
    }

    // gbar: warp w handles l = l0 + w*4 + i (4 rows per warp)
    const int w = threadIdx.x >> 5, lane = threadIdx.x & 31;
#pragma unroll
    for (int i = 0; i < 4; i++) {
        const int l = l0 + w * 4 + i;
        const size_t base = ((size_t)b * L_ + l) * C3_ + 2 * C_;
        float s = 0.f;
#pragma unroll
        for (int c = lane; c < C_; c += 32)
            s += __bfloat162float(inHi[base + c]) + __bfloat162float(inLo[base + c]);
        s = warpSum(s);
        if (lane == 0) gbar[b * L_ + l] = s * (1.f / C_);
    }
}

// ============================================================================
// Fused: softmax(Sg row) -> gp hi/lo  AND  banded local gate from Sl row.
// ============================================================================
__global__ void softmax_gate(const float* __restrict__ Sg,
                             const float* __restrict__ Sl,
                             const float* __restrict__ gbar,
                             const float* __restrict__ wlw,
                             const float* __restrict__ wlb,
                             __nv_bfloat16* __restrict__ pHi,
                             __nv_bfloat16* __restrict__ pLo,
                             float* __restrict__ gate)
{
    __shared__ float sm[16];
    const int l = blockIdx.x, b = blockIdx.y, tid = threadIdx.x;
    const int lane = tid & 31, w = tid >> 5;
    const size_t row = (size_t)b * L_ + l;

    float v = Sg[row * L_ + tid];
    float m = warpMax(v);
    if (lane == 0) sm[w] = m;
    __syncthreads();
    float M = -1e30f;
#pragma unroll
    for (int i = 0; i < 8; i++) M = fmaxf(M, sm[i]);
    float e = __expf(v - M);
    float s = warpSum(e);
    if (lane == 0) sm[8 + w] = s;
    __syncthreads();
    float T = 0.f;
#pragma unroll
    for (int i = 0; i < 8; i++) T += sm[8 + i];
    float p = e / T;
    __nv_bfloat16 h = __float2bfloat16(p);
    pHi[row * L_ + tid] = h;
    pLo[row * L_ + tid] = __float2bfloat16(p - __bfloat162float(h));

    if (w == 0) {
        const float* srow = Sl + row * L_;
        const float* gb = gbar + (size_t)b * L_;
        int m0 = l + lane - 32;
        int m1 = l + lane;
        bool v0 = (m0 >= 0) && (m0 < L_);
        bool v1 = (m1 >= 0) && (m1 < L_);
        float s0 = v0 ? srow[m0] : 0.f;
        float s1 = v1 ? srow[m1] : 0.f;
        float g0 = v0 ? gb[m0] : 0.f;
        float g1 = v1 ? gb[m1] : 0.f;
        float mx = warpMax(fmaxf(s0, s1));
        float e0 = __expf(s0 - mx), e1 = __expf(s1 - mx);
        float num = warpSum(e0 * g0 + e1 * g1);
        float den = warpSum(e0 + e1);
        if (lane == 0) {
            float pooled = num / den;
            float z = wlw[0] * pooled + wlb[0];
            gate[b * L_ + l] = 1.f / (1.f + __expf(-z));
        }
    }
}

// ============================================================================
// LN1: h = gout2T*gate + x ; h1 fp32 + bf16 hi/lo at row (l*B+b), [*,C]
// ============================================================================
__global__ void ln1_kernel(const float* __restrict__ gout2T,
                           const float* __restrict__ gate,
                           const float* __restrict__ x,
                           const float* __restrict__ g1, const float* __restrict__ b1,
                           float* __restrict__ h1,
                           __nv_bfloat16* __restrict__ h1hi,
                           __nv_bfloat16* __restrict__ h1lo)
{
    __shared__ float sm[16];
    int l = blockIdx.x, b = blockIdx.y, tid = threadIdx.x;
    int lane = tid & 31, w = tid >> 5;
    float gt = gate[b * L_ + l];
    size_t gbase = ((size_t)b * L_ + l) * C_;
    size_t xbase = (size_t)b * CL_ + l;
    float v0 = fmaf(gout2T[gbase + tid], gt, x[xbase + (size_t)tid * L_]);
    float v1 = fmaf(gout2T[gbase + tid + 256], gt, x[xbase + (size_t)(tid + 256) * L_]);
    float s = warpSum(v0 + v1);
    float q = warpSum(v0 * v0 + v1 * v1);
    if (lane == 0) { sm[w] = s; sm[8 + w] = q; }
    __syncthreads();
    float S = 0.f, Q = 0.f;
#pragma unroll
    for (int i = 0; i < 8; i++) { S += sm[i]; Q += sm[8 + i]; }
    float mean = S * (1.f / C_);
    float var = Q * (1.f / C_) - mean * mean;
    float r = rsqrtf(var + 1e-5f);
    size_t o = ((size_t)l * B_ + b) * C_;
    float y0 = (v0 - mean) * r * g1[tid] + b1[tid];
    float y1 = (v1 - mean) * r * g1[tid + 256] + b1[tid + 256];
    h1[o + tid] = y0;
    h1[o + tid + 256] = y1;
    __nv_bfloat16 h0b = __float2bfloat16(y0);
    __nv_bfloat16 h1b = __float2bfloat16(y1);
    h1hi[o + tid] = h0b;
    h1hi[o + tid + 256] = h1b;
    h1lo[o + tid] = __float2bfloat16(y0 - __bfloat162float(h0b));
    h1lo[o + tid + 256] = __float2bfloat16(y1 - __bfloat162float(h1b));
}

// ============================================================================
// LN2 + output transpose
// ============================================================================
__global__ void ln2_kernel(const float* __restrict__ m2,
                           const float* __restrict__ h1,
                           const float* __restrict__ g2, const float* __restrict__ b2,
                           float* __restrict__ out)
{
    __shared__ float sm[16];
    int row = blockIdx.x, tid = threadIdx.x;
    int lane = tid & 31, w = tid >> 5;
    int l = row / B_, b = row % B_;
    size_t base = (size_t)row * C_;
    float v0 = m2[base + tid] + h1[base + tid];
    float v1 = m2[base + tid + 256] + h1[base + tid + 256];
    float s = warpSum(v0 + v1);
    float q = warpSum(v0 * v0 + v1 * v1);
    if (lane == 0) { sm[w] = s; sm[8 + w] = q; }
    __syncthreads();
    float S = 0.f, Q = 0.f;
#pragma unroll
    for (int i = 0; i < 8; i++) { S += sm[i]; Q += sm[8 + i]; }
    float mean = S * (1.f / C_);
    float var = Q * (1.f / C_) - mean * mean;
    float r = rsqrtf(var + 1e-5f);
    size_t ob = (size_t)b * CL_ + l;
    out[ob + (size_t)tid * L_]         = (v0 - mean) * r * g2[tid] + b2[tid];
    out[ob + (size_t)(tid + 256) * L_] = (v1 - mean) * r * g2[tid + 256] + b2[tid + 256];
}

} // namespace

// ============================================================================
// Host launcher
// ============================================================================
extern "C" void kernel_launch(void* const* d_in, const int* in_sizes, int n_in,
                              void* d_out, int out_size)
{
    (void)in_sizes; (void)n_in; (void)out_size;
    float* scratch = nullptr;
    cudaGetSymbolAddress((void**)&scratch, d_scratch);

    const float* x       = (const float*)d_in[0];
    const float* theta_w = (const float*)d_in[1];
    const float* theta_b = (const float*)d_in[2];
    const float* phi_w   = (const float*)d_in[3];
    const float* phi_b   = (const float*)d_in[4];
    const float* g_w     = (const float*)d_in[5];
    const float* g_b     = (const float*)d_in[6];
    const float* wl_w    = (const float*)d_in[7];
    const float* wl_b    = (const float*)d_in[8];
    const float* wg_w    = (const float*)d_in[9];
    const float* wg_b    = (const float*)d_in[10];
    const float* conv1_w = (const float*)d_in[11];
    const float* conv1_b = (const float*)d_in[12];
    const float* conv2_w = (const float*)d_in[13];
    const float* conv2_b = (const float*)d_in[14];
    const float* ln1_g   = (const float*)d_in[15];
    const float* ln1_b   = (const float*)d_in[16];
    const float* ln2_g   = (const float*)d_in[17];
    const float* ln2_b   = (const float*)d_in[18];
    float* out = (float*)d_out;

    __nv_bfloat16* xtHi   = (__nv_bfloat16*)(scratch + OFF_XT_HI);
    __nv_bfloat16* xtLo   = (__nv_bfloat16*)(scratch + OFF_XT_LO);
    __nv_bfloat16* wqkvHi = (__nv_bfloat16*)(scratch + OFF_WQKV_HI);
    __nv_bfloat16* wqkvLo = (__nv_bfloat16*)(scratch + OFF_WQKV_LO);
    float* qkv_b          = scratch + OFF_QKV_B;
    __nv_bfloat16* wwgHi  = (__nv_bfloat16*)(scratch + OFF_WWG_HI);
    __nv_bfloat16* wwgLo  = (__nv_bfloat16*)(scratch + OFF_WWG_LO);
    __nv_bfloat16* c1wHi  = (__nv_bfloat16*)(scratch + OFF_C1WHI);
    __nv_bfloat16* c1wLo  = (__nv_bfloat16*)(scratch + OFF_C1WLO);
    __nv_bfloat16* c2wHi  = (__nv_bfloat16*)(scratch + OFF_C2WHI);
    __nv_bfloat16* c2wLo  = (__nv_bfloat16*)(scratch + OFF_C2WLO);
    __nv_bfloat16* qkvHi  = (__nv_bfloat16*)(scratch + OFF_QKVT_HI);
    __nv_bfloat16* qkvLo  = (__nv_bfloat16*)(scratch + OFF_QKVT_LO);
    float* Sg    = scratch + OFF_SG;
    __nv_bfloat16* gpHi   = (__nv_bfloat16*)(scratch + OFF_GP_HI);
    __nv_bfloat16* gpLo   = (__nv_bfloat16*)(scratch + OFF_GP_LO);
    __nv_bfloat16* gg2Hi  = (__nv_bfloat16*)(scratch + OFF_GG2_HI);
    __nv_bfloat16* gg2Lo  = (__nv_bfloat16*)(scratch + OFF_GG2_LO);
    float* gbar  = scratch + OFF_GBAR;
    float* gate  = scratch + OFF_GATE;
    __nv_bfloat16* goHi   = (__nv_bfloat16*)(scratch + OFF_GOUTT_HI);
    __nv_bfloat16* goLo   = (__nv_bfloat16*)(scratch + OFF_GOUTT_LO);
    float* gout2T = scratch + OFF_GOUT2T;
    float* h1    = scratch + OFF_H1;
    __nv_bfloat16* h1Hi   = (__nv_bfloat16*)(scratch + OFF_H1HI);
    __nv_bfloat16* h1Lo   = (__nv_bfloat16*)(scratch + OFF_H1LO);
    __nv_bfloat16* m1Hi   = (__nv_bfloat16*)(scratch + OFF_M1HI);
    __nv_bfloat16* m1Lo   = (__nv_bfloat16*)(scratch + OFF_M1LO);
    float* m2    = scratch + OFF_M2;

    // BN=64, KB=64, 3 stages: SROW=144, stage = 2*18432 + 2*9216 = 55296; x3
    constexpr int SMEM64_K64  = 165888;
    // BN=128, KB=32, 2 stages: stage = 40960; x2 (2 CTAs/SM)
    constexpr int SMEM128_K32 = 81920;
    cudaFuncSetAttribute(gemm_mma<64, 0, 0, 1, 3, 64>,  cudaFuncAttributeMaxDynamicSharedMemorySize, SMEM64_K64);
    cudaFuncSetAttribute(gemm_mma<64, 1, 0, 0, 3, 64>,  cudaFuncAttributeMaxDynamicSharedMemorySize, SMEM64_K64);
    cudaFuncSetAttribute(gemm_mma<64, 0, 0, 0, 3, 64>,  cudaFuncAttributeMaxDynamicSharedMemorySize, SMEM64_K64);
    cudaFuncSetAttribute(gemm_mma<128, 1, 0, 0, 2, 32>, cudaFuncAttributeMaxDynamicSharedMemorySize, SMEM128_K32);
    cudaFuncSetAttribute(gemm_mma<128, 1, 1, 0, 2, 32>, cudaFuncAttributeMaxDynamicSharedMemorySize, SMEM128_K32);

    // 0) prep: all splits + bias concat + x transpose in ONE launch
    prep_all<<<PREP_NSPLIT + PREP_NT, 256>>>(
        x, theta_w, phi_w, g_w, wg_w, conv1_w, conv2_w, theta_b, phi_b, g_b,
        wqkvHi, wqkvLo, wwgHi, wwgLo, c1wHi, c1wLo, c2wHi, c2wLo, qkv_b, xtHi, xtLo);

    // 1) fused qkv (BN=128): qkvT[b,l,:] = xT(b) @ [th;ph;g]^T + bias
    {
        dim3 grid(C3_ / 128, L_ / 128, B_);
        gemm_mma<128, 1, 0, 0, 2, 32><<<grid, 256, SMEM128_K32>>>(
            xtHi, xtLo, wqkvHi, wqkvLo, qkv_b, nullptr, qkvHi, qkvLo,
            C_, C_, C_, C3_, (size_t)L_ * C_, 0, (size_t)L_ * C3_, 0, 0, 1.f);
    }

    // 2) g transpose + gbar in one launch
    gtrans_gbar<<<dim3(L_ / 32, B_), 256>>>(qkvHi, qkvLo, gg2Hi, gg2Lo, gbar);

    // 3) Sg & Sl in ONE launch (sel = z>>3: 0 -> theta/Sg, 1 -> g/Sl)
    {
        dim3 grid(L_ / 64, L_ / 128, 2 * B_);
        gemm_mma<64, 0, 0, 1, 3, 64><<<grid, 256, SMEM64_K64>>>(
            qkvHi + C_, qkvLo + C_, qkvHi, qkvLo, nullptr, Sg, nullptr, nullptr,
            C_, C3_, C3_, L_, (size_t)L_ * C3_, (size_t)L_ * C3_, (size_t)L_ * L_,
            (size_t)(2 * C_), (size_t)B_ * L_ * L_, SCALE_);
    }

    // 4) fused softmax + local gate
    softmax_gate<<<dim3(L_, B_), 256>>>(Sg, Sg + (size_t)B_ * L_ * L_, gbar,
                                        wl_w, wl_b, gpHi, gpLo, gate);

    // 5) goutT = gp @ gg2^T (hi/lo) ; gout2T = goutT @ wg^T + wg_b (fp32)
    {
        dim3 grid(C_ / 64, L_ / 128, B_);
        gemm_mma<64, 1, 0, 0, 3, 64><<<grid, 256, SMEM64_K64>>>(
            gpHi, gpLo, gg2Hi, gg2Lo, nullptr, nullptr, goHi, goLo,
            L_, L_, L_, C_, (size_t)L_ * L_, (size_t)CL_, (size_t)L_ * C_, 0, 0, 1.f);
        gemm_mma<64, 0, 0, 0, 3, 64><<<grid, 256, SMEM64_K64>>>(
            goHi, goLo, wwgHi, wwgLo, wg_b, gout2T, nullptr, nullptr,
            C_, C_, C_, C_, (size_t)L_ * C_, 0, (size_t)L_ * C_, 0, 0, 1.f);
    }

    // 6) LN1 -> h1 (fp32 + hi/lo)
    ln1_kernel<<<dim3(L_, B_), 256>>>(gout2T, gate, x, ln1_g, ln1_b, h1, h1Hi, h1Lo);

    // 7) MLP1: m1 = Mish(h1 @ conv1^T + b) -> hi/lo
    {
        dim3 grid(C4_ / 128, NR_ / 128, 1);
        gemm_mma<128, 1, 1, 0, 2, 32><<<grid, 256, SMEM128_K32>>>(
            h1Hi, h1Lo, c1wHi, c1wLo, conv1_b, nullptr, m1Hi, m1Lo,
            C_, C_, C_, C4_, 0, 0, 0, 0, 0, 1.f);
    }

    // 8) MLP2: m2 = m1 @ conv2^T + b -> fp32
    {
        dim3 grid(C_ / 64, NR_ / 128, 1);
        gemm_mma<64, 0, 0, 0, 3, 64><<<grid, 256, SMEM64_K64>>>(
            m1Hi, m1Lo, c2wHi, c2wLo, conv2_b, m2, nullptr, nullptr,
            C4_, C4_, C4_, C_, 0, 0, 0, 0, 0, 1.f);
    }

    // 9) LN2 + transpose out
    ln2_kernel<<<NR_, 256>>>(m2, h1, ln2_g, ln2_b, out);
}